// round 6
// baseline (speedup 1.0000x reference)
#include <cuda_runtime.h>
#include <cstdint>

#define N     8192
#define FIN   512
#define FO    64
#define NW    256             // mask words per row
#define NEG_BIG (-9e15f)
#define INVN  (1.0f/8192.0f)
#define KS    8               // K-splits in k_main

// ---- scratch ----
__device__ float    g_Wh[N*FO];
__device__ float    g_Wh1[N];
__device__ float    g_Wh2[N];
__device__ float    g_B[N];           // exp(wh2)
__device__ float    g_D[N];           // exp(0.2*wh2)
__device__ float    g_add[N];
__device__ float    g_cpm[N], g_ncm[N], g_cpn[N], g_ncn[N];
__device__ unsigned g_mask[N*NW];
__device__ unsigned g_maskn[N*NW];
__device__ float    g_hp[N*FO];

__device__ __forceinline__ uint32_t tf32bits(float x) {
    uint32_t r; asm("cvt.rna.tf32.f32 %0, %1;" : "=r"(r) : "f"(x)); return r;
}
__device__ __forceinline__ void mma_tf32(float* d,
        uint32_t a0, uint32_t a1, uint32_t a2, uint32_t a3,
        uint32_t b0, uint32_t b1) {
    asm volatile("mma.sync.aligned.m16n8k8.row.col.f32.tf32.tf32.f32 "
        "{%0,%1,%2,%3}, {%4,%5,%6,%7}, {%8,%9}, {%0,%1,%2,%3};"
        : "+f"(d[0]), "+f"(d[1]), "+f"(d[2]), "+f"(d[3])
        : "r"(a0), "r"(a1), "r"(a2), "r"(a3), "r"(b0), "r"(b1));
}

// ============================================================
// Kernel 1: Wh = h @ W ; Wh1 ; Wh2
// ============================================================
__global__ void k_gemm1(const float* __restrict__ h,
                        const float* __restrict__ W,
                        const float* __restrict__ a) {
    __shared__ float a_s[2*FO];
    __shared__ float r1[8][2], r2[8][2];
    int t = threadIdx.x;
    if (t < 2*FO) a_s[t] = a[t];
    int row = t >> 6;
    int f   = t & 63;
    int i   = blockIdx.x * 8 + row;
    __syncthreads();

    const float* hrow = h + (size_t)i * FIN;
    float acc = 0.f;
    #pragma unroll 4
    for (int k = 0; k < FIN; k += 4) {
        float4 hv = *reinterpret_cast<const float4*>(hrow + k);
        acc += hv.x * W[(k+0)*FO + f];
        acc += hv.y * W[(k+1)*FO + f];
        acc += hv.z * W[(k+2)*FO + f];
        acc += hv.w * W[(k+3)*FO + f];
    }
    g_Wh[(size_t)i*FO + f] = acc;

    float p1 = acc * a_s[f];
    float p2 = acc * a_s[FO + f];
    #pragma unroll
    for (int off = 16; off; off >>= 1) {
        p1 += __shfl_down_sync(0xffffffffu, p1, off);
        p2 += __shfl_down_sync(0xffffffffu, p2, off);
    }
    int w = t >> 5;
    if ((t & 31) == 0) { r1[w>>1][w&1] = p1; r2[w>>1][w&1] = p2; }
    __syncthreads();
    if (t < 8) {
        g_Wh1[blockIdx.x*8 + t] = r1[t][0] + r1[t][1];
        g_Wh2[blockIdx.x*8 + t] = r2[t][0] + r2[t][1];
    }
}

// ============================================================
// Kernel 1b: B[j] = exp(wh2_j), D[j] = exp(0.2 wh2_j)
// ============================================================
__global__ void k_prep() {
    int tid = blockIdx.x * 256 + threadIdx.x;
    float w2a = g_Wh2[2*tid], w2b = g_Wh2[2*tid+1];
    g_B[2*tid]   = expf(w2a);
    g_B[2*tid+1] = expf(w2b);
    g_D[2*tid]   = expf(0.2f * w2a);
    g_D[2*tid+1] = expf(0.2f * w2b);
}

// ============================================================
// Kernel 2a: PURE ballot-pack of adj/adj_new (DRAM-bound)
// 256 thr = 8 warps = 8 rows; grid N/8
// ============================================================
__global__ void k_pack(const int* __restrict__ adj,
                       const int* __restrict__ adjn) {
    int lane = threadIdx.x & 31;
    int i    = blockIdx.x * 8 + (threadIdx.x >> 5);
    const int* arow = adj  + (size_t)i * N;
    const int* nrow = adjn + (size_t)i * N;
    int sh = (lane & 7) * 4;

    #pragma unroll 2
    for (int k = 0; k < N/128; k++) {
        int jb = k*128 + lane*4;
        int4 av = *reinterpret_cast<const int4*>(&arow[jb]);
        int4 nv = *reinterpret_cast<const int4*>(&nrow[jb]);
        unsigned nm = (unsigned)(av.x > 0)
                    | ((unsigned)(av.y > 0) << 1)
                    | ((unsigned)(av.z > 0) << 2)
                    | ((unsigned)(av.w > 0) << 3);
        unsigned nn = (unsigned)(nv.x > 0)
                    | ((unsigned)(nv.y > 0) << 1)
                    | ((unsigned)(nv.z > 0) << 2)
                    | ((unsigned)(nv.w > 0) << 3);
        unsigned vm = nm << sh;
        unsigned vn = nn << sh;
        vm |= __shfl_xor_sync(0xffffffffu, vm, 1);
        vn |= __shfl_xor_sync(0xffffffffu, vn, 1);
        vm |= __shfl_xor_sync(0xffffffffu, vm, 2);
        vn |= __shfl_xor_sync(0xffffffffu, vn, 2);
        vm |= __shfl_xor_sync(0xffffffffu, vm, 4);
        vn |= __shfl_xor_sync(0xffffffffu, vn, 4);
        if ((lane & 7) == 0) {
            g_mask [(size_t)i*NW + k*4 + (lane>>3)] = vm;
            g_maskn[(size_t)i*NW + k*4 + (lane>>3)] = vn;
        }
    }
}

// ============================================================
// Kernel 2b: softmax stats from L2-resident masks.
// lane l owns bit l; warp per row; grid N/8 x 256 thr.
// Single UNION max (base only needs max over adj|adj_new).
// Also zeroes g_hp.
// ============================================================
__global__ void k_stats2() {
    int tid = blockIdx.x * 256 + threadIdx.x;
    g_hp[2*tid]     = 0.f;
    g_hp[2*tid + 1] = 0.f;

    int lane = threadIdx.x & 31;
    int i    = blockIdx.x * 8 + (threadIdx.x >> 5);
    float wh1 = g_Wh1[i];
    float thr = -wh1;
    const unsigned* mrow = &g_mask [(size_t)i*NW];
    const unsigned* nrow = &g_maskn[(size_t)i*NW];

    float Mu = NEG_BIG;
    float Smp = 0.f, Smn = 0.f, Snp = 0.f, Snn = 0.f;

    #pragma unroll 4
    for (int k = 0; k < NW; k++) {
        unsigned wm = mrow[k];
        unsigned wn = nrow[k];
        int j = k*32 + lane;
        float w2 = g_Wh2[j];
        float Bv = g_B[j];
        float Dv = g_D[j];
        bool bm = (wm >> lane) & 1u;
        bool bn = (wn >> lane) & 1u;
        bool p  = w2 > thr;
        if (bm | bn) Mu = fmaxf(Mu, w2);
        float val = p ? Bv : Dv;
        if (bm) { if (p) Smp += val; else Smn += val; }
        if (bn) { if (p) Snp += val; else Snn += val; }
    }
    #pragma unroll
    for (int off = 16; off; off >>= 1) {
        Mu  = fmaxf(Mu, __shfl_xor_sync(0xffffffffu, Mu, off));
        Smp += __shfl_xor_sync(0xffffffffu, Smp, off);
        Smn += __shfl_xor_sync(0xffffffffu, Smn, off);
        Snp += __shfl_xor_sync(0xffffffffu, Snp, off);
        Snn += __shfl_xor_sync(0xffffffffu, Snn, off);
    }
    if (lane == 0) {
        float x = wh1 + Mu;
        float base = (Mu > 0.5f*NEG_BIG) ? (x > 0.f ? x : 0.2f * x) : 0.f;
        float ep = expf(wh1 - base);
        float en = expf(0.2f * wh1 - base);
        float dm = ep * Smp + en * Smn;
        float dn = ep * Snp + en * Snn;
        float km = (dm > 0.f) ? 1.f / dm : 0.f;
        float kn = (dn > 0.f) ? 1.f / dn : 0.f;
        g_add[i] = ((dm > 0.f) ? 0.f : INVN) + ((dn > 0.f) ? 0.f : INVN);
        g_cpm[i] = ep * km;  g_ncm[i] = en * km;
        g_cpn[i] = ep * kn;  g_ncn[i] = en * kn;
    }
}

// ============================================================
// Kernel 3: fused attention + tf32 mma.sync (attn @ Wh)
// grid (KS, N/64); 128 thr = 4 warps x 16 rows
// B operand pair-packed as uint2 -> one LDS.64 per mma
// ============================================================
__device__ __forceinline__ float attn_val(float w2, float Bj, float Dj,
        float thr, float add, float cpm, float ncm, float cpn, float ncn,
        unsigned mb, unsigned nb) {
    bool  p  = w2 > thr;
    float E  = p ? Bj : Dj;
    float cm = p ? cpm : ncm;
    float cn = p ? cpn : ncn;
    float wg = ((mb & 1u) ? cm : 0.f) + ((nb & 1u) ? cn : 0.f);
    return fmaf(E, wg, add);
}

__global__ void __launch_bounds__(128, 4) k_main(float* __restrict__ attn) {
    // whs2[f][p] : pair (Wh[jp][f], Wh[jp+4][f]) tf32; jp = 8*(p>>2)+(p&3)
    // row stride 36 uint2 (72 words) -> bank8(f,p) = (4f+p) mod 32, conflict-free
    __shared__ uint2 whs2[64*36];              // 18.4 KB
    __shared__ float at_s[64*68];              // 17.4 KB
    __shared__ float Bs[64], Ds[64], w2s[64];

    int t = threadIdx.x, w = t >> 5, lane = t & 31;
    int g = lane >> 2, c = lane & 3;
    int i0 = blockIdx.y * 64;
    int rel0 = w*16 + g, rel1 = rel0 + 8;
    int r0 = i0 + rel0, r1 = i0 + rel1;

    float thr0 = -g_Wh1[r0],  thr1 = -g_Wh1[r1];
    float add0 = g_add[r0],   add1 = g_add[r1];
    float cpm0 = g_cpm[r0], ncm0 = g_ncm[r0], cpn0 = g_cpn[r0], ncn0 = g_ncn[r0];
    float cpm1 = g_cpm[r1], ncm1 = g_ncm[r1], cpn1 = g_cpn[r1], ncn1 = g_ncn[r1];

    float acc[8][4];
    #pragma unroll
    for (int nt = 0; nt < 8; nt++)
        #pragma unroll
        for (int q = 0; q < 4; q++) acc[nt][q] = 0.f;

    int jcta = blockIdx.x * (N/KS);
    uint32_t* whsw = reinterpret_cast<uint32_t*>(whs2);

    for (int tt = 0; tt < (N/KS)/64; tt++) {
        int j0 = jcta + tt*64;
        __syncthreads();
        // stage Wh tile (64 j x 64 f) into pair-packed layout
        #pragma unroll
        for (int q = 0; q < 8; q++) {
            int idx = t + 128*q;
            int r = idx >> 4, c4 = (idx & 15) * 4;   // r = j, c4 = f base
            float4 v = *reinterpret_cast<const float4*>(&g_Wh[(size_t)(j0+r)*FO + c4]);
            int p  = ((r >> 3) << 2) + (r & 3);
            int hi = (r >> 2) & 1;
            int base = p*2 + hi;
            whsw[(c4+0)*72 + base] = tf32bits(v.x);
            whsw[(c4+1)*72 + base] = tf32bits(v.y);
            whsw[(c4+2)*72 + base] = tf32bits(v.z);
            whsw[(c4+3)*72 + base] = tf32bits(v.w);
        }
        if (t < 64) { Bs[t] = g_B[j0+t]; Ds[t] = g_D[j0+t]; w2s[t] = g_Wh2[j0+t]; }
        __syncthreads();

        int wb = j0 >> 5;
        uint2 mw0 = *reinterpret_cast<const uint2*>(&g_mask [(size_t)r0*NW + wb]);
        uint2 nw0 = *reinterpret_cast<const uint2*>(&g_maskn[(size_t)r0*NW + wb]);
        uint2 mw1 = *reinterpret_cast<const uint2*>(&g_mask [(size_t)r1*NW + wb]);
        uint2 nw1 = *reinterpret_cast<const uint2*>(&g_maskn[(size_t)r1*NW + wb]);

        #pragma unroll
        for (int kk = 0; kk < 8; kk++) {
            int jA = kk*8 + c, jB = jA + 4;
            float BA = Bs[jA], DA = Ds[jA], wA = w2s[jA];
            float BB = Bs[jB], DB = Ds[jB], wB = w2s[jB];
            unsigned m0 = (kk < 4) ? mw0.x : mw0.y;
            unsigned n0 = (kk < 4) ? nw0.x : nw0.y;
            unsigned m1 = (kk < 4) ? mw1.x : mw1.y;
            unsigned n1 = (kk < 4) ? nw1.x : nw1.y;
            int sA = (kk & 3)*8 + c, sB = sA + 4;

            float v00 = attn_val(wA, BA, DA, thr0, add0, cpm0, ncm0, cpn0, ncn0, m0>>sA, n0>>sA);
            float v10 = attn_val(wA, BA, DA, thr1, add1, cpm1, ncm1, cpn1, ncn1, m1>>sA, n1>>sA);
            float v01 = attn_val(wB, BB, DB, thr0, add0, cpm0, ncm0, cpn0, ncn0, m0>>sB, n0>>sB);
            float v11 = attn_val(wB, BB, DB, thr1, add1, cpm1, ncm1, cpn1, ncn1, m1>>sB, n1>>sB);

            at_s[rel0*68 + jA] = v00;  at_s[rel0*68 + jB] = v01;
            at_s[rel1*68 + jA] = v10;  at_s[rel1*68 + jB] = v11;

            uint32_t a0 = tf32bits(v00), a1 = tf32bits(v10);
            uint32_t a2 = tf32bits(v01), a3 = tf32bits(v11);

            #pragma unroll
            for (int nt = 0; nt < 8; nt++) {
                uint2 b = whs2[(nt*8 + g)*36 + kk*4 + c];
                mma_tf32(acc[nt], a0, a1, a2, a3, b.x, b.y);
            }
        }
        __syncthreads();

        // coalesced copy-out: 64x64 tile = 1024 float4, 8 per thread
        #pragma unroll
        for (int q = 0; q < 8; q++) {
            int idx = t + 128*q;
            int row = idx >> 4, c4 = (idx & 15) * 4;
            float4 v = *reinterpret_cast<const float4*>(&at_s[row*68 + c4]);
            *reinterpret_cast<float4*>(&attn[(size_t)(i0+row)*N + j0 + c4]) = v;
        }
    }

    #pragma unroll
    for (int nt = 0; nt < 8; nt++) {
        atomicAdd(&g_hp[(size_t)r0*FO + nt*8 + 2*c    ], acc[nt][0]);
        atomicAdd(&g_hp[(size_t)r0*FO + nt*8 + 2*c + 1], acc[nt][1]);
        atomicAdd(&g_hp[(size_t)r1*FO + nt*8 + 2*c    ], acc[nt][2]);
        atomicAdd(&g_hp[(size_t)r1*FO + nt*8 + 2*c + 1], acc[nt][3]);
    }
}

// ============================================================
// Kernel 4: out = elu(h_prime)
// ============================================================
__global__ void k_elu(float* __restrict__ out) {
    int tid = blockIdx.x * 256 + threadIdx.x;
    float x = g_hp[tid];
    out[tid] = x > 0.f ? x : expm1f(x);
}

// ============================================================
extern "C" void kernel_launch(void* const* d_in, const int* in_sizes, int n_in,
                              void* d_out, int out_size) {
    const float* h    = (const float*)d_in[0];
    const float* W    = (const float*)d_in[1];
    const float* a    = (const float*)d_in[2];
    const int*   adj  = (const int*)d_in[3];
    const int*   adjn = (const int*)d_in[4];

    float* out  = (float*)d_out;
    float* attn = out + (size_t)N * FO;

    k_gemm1<<<N/8, 512>>>(h, W, a);
    k_prep<<<N/512, 256>>>();
    k_pack<<<N/8, 256>>>(adj, adjn);
    k_stats2<<<N/8, 256>>>();
    k_main<<<dim3(KS, N/64), 128>>>(attn);
    k_elu<<<(N*FO)/256, 256>>>(out);
}

// round 7
// speedup vs baseline: 1.4433x; 1.4433x over previous
#include <cuda_runtime.h>
#include <cstdint>

#define N     8192
#define FIN   512
#define FO    64
#define NW    256             // mask words per row
#define INVN  (1.0f/8192.0f)
#define KS    4               // K-splits in k_main

// ---- scratch ----
__device__ float    g_Wh[N*FO];
__device__ float    g_Wh1[N];
__device__ float    g_Wh2[N];
__device__ float2   g_BD[N];          // (exp(wh2), exp(0.2*wh2))
__device__ float    g_add[N];
__device__ float    g_ep[N], g_en[N]; // exp(wh1), exp(0.2*wh1)
__device__ float    g_km[N], g_kn[N]; // 1/dm, 1/dn
__device__ unsigned g_mask[N*NW];
__device__ unsigned g_maskn[N*NW];
__device__ float    g_hp[N*FO];

__device__ __forceinline__ uint32_t tf32bits(float x) {
    uint32_t r; asm("cvt.rna.tf32.f32 %0, %1;" : "=r"(r) : "f"(x)); return r;
}
__device__ __forceinline__ void mma_tf32(float* d,
        uint32_t a0, uint32_t a1, uint32_t a2, uint32_t a3,
        uint32_t b0, uint32_t b1) {
    asm volatile("mma.sync.aligned.m16n8k8.row.col.f32.tf32.tf32.f32 "
        "{%0,%1,%2,%3}, {%4,%5,%6,%7}, {%8,%9}, {%0,%1,%2,%3};"
        : "+f"(d[0]), "+f"(d[1]), "+f"(d[2]), "+f"(d[3])
        : "r"(a0), "r"(a1), "r"(a2), "r"(a3), "r"(b0), "r"(b1));
}

// ============================================================
// Kernel 1: Wh = h @ W ; Wh1 ; Wh2
// ============================================================
__global__ void k_gemm1(const float* __restrict__ h,
                        const float* __restrict__ W,
                        const float* __restrict__ a) {
    __shared__ float a_s[2*FO];
    __shared__ float r1[8][2], r2[8][2];
    int t = threadIdx.x;
    if (t < 2*FO) a_s[t] = a[t];
    int row = t >> 6;
    int f   = t & 63;
    int i   = blockIdx.x * 8 + row;
    __syncthreads();

    const float* hrow = h + (size_t)i * FIN;
    float acc = 0.f;
    #pragma unroll 4
    for (int k = 0; k < FIN; k += 4) {
        float4 hv = *reinterpret_cast<const float4*>(hrow + k);
        acc += hv.x * W[(k+0)*FO + f];
        acc += hv.y * W[(k+1)*FO + f];
        acc += hv.z * W[(k+2)*FO + f];
        acc += hv.w * W[(k+3)*FO + f];
    }
    g_Wh[(size_t)i*FO + f] = acc;

    float p1 = acc * a_s[f];
    float p2 = acc * a_s[FO + f];
    #pragma unroll
    for (int off = 16; off; off >>= 1) {
        p1 += __shfl_down_sync(0xffffffffu, p1, off);
        p2 += __shfl_down_sync(0xffffffffu, p2, off);
    }
    int w = t >> 5;
    if ((t & 31) == 0) { r1[w>>1][w&1] = p1; r2[w>>1][w&1] = p2; }
    __syncthreads();
    if (t < 8) {
        g_Wh1[blockIdx.x*8 + t] = r1[t][0] + r1[t][1];
        g_Wh2[blockIdx.x*8 + t] = r2[t][0] + r2[t][1];
    }
}

// ============================================================
// Kernel 1b: BD[j] = (exp(wh2_j), exp(0.2 wh2_j))
// ============================================================
__global__ void k_prep() {
    int tid = blockIdx.x * 256 + threadIdx.x;
    float w2 = g_Wh2[tid];
    g_BD[tid] = make_float2(expf(w2), expf(0.2f * w2));
}

// ============================================================
// Kernel 2: FUSED adj pass: ballot-pack + unnormalized softmax
// sums (base=0; exp(lrelu(x)) = max(ep*B, en*D)).
// 256 thr = 8 warps = 8 rows; grid N/8. Also zeroes g_hp.
// ============================================================
__global__ void k_spack(const int* __restrict__ adj,
                        const int* __restrict__ adjn) {
    int tid = blockIdx.x * 256 + threadIdx.x;
    g_hp[2*tid]     = 0.f;
    g_hp[2*tid + 1] = 0.f;

    int lane = threadIdx.x & 31;
    int i    = blockIdx.x * 8 + (threadIdx.x >> 5);
    float wh1 = g_Wh1[i];
    float ep = expf(wh1);
    float en = expf(0.2f * wh1);
    const int* arow = adj  + (size_t)i * N;
    const int* nrow = adjn + (size_t)i * N;
    int sh = (lane & 7) * 4;

    float Sm0 = 0.f, Sm1 = 0.f, Sn0 = 0.f, Sn1 = 0.f;

    #pragma unroll 2
    for (int k = 0; k < N/128; k++) {
        int jb = k*128 + lane*4;
        int4   av  = *reinterpret_cast<const int4*>(&arow[jb]);
        int4   nv  = *reinterpret_cast<const int4*>(&nrow[jb]);
        float4 bd0 = *reinterpret_cast<const float4*>(&g_BD[jb]);      // B0 D0 B1 D1
        float4 bd1 = *reinterpret_cast<const float4*>(&g_BD[jb + 2]);  // B2 D2 B3 D3

        float v0 = fmaxf(ep*bd0.x, en*bd0.y);
        float v1 = fmaxf(ep*bd0.z, en*bd0.w);
        float v2 = fmaxf(ep*bd1.x, en*bd1.y);
        float v3 = fmaxf(ep*bd1.z, en*bd1.w);

        bool bm0 = av.x > 0, bm1 = av.y > 0, bm2 = av.z > 0, bm3 = av.w > 0;
        bool bn0 = nv.x > 0, bn1 = nv.y > 0, bn2 = nv.z > 0, bn3 = nv.w > 0;

        if (bm0) Sm0 += v0;   if (bm1) Sm1 += v1;
        if (bm2) Sm0 += v2;   if (bm3) Sm1 += v3;
        if (bn0) Sn0 += v0;   if (bn1) Sn1 += v1;
        if (bn2) Sn0 += v2;   if (bn3) Sn1 += v3;

        unsigned nm = (unsigned)bm0 | ((unsigned)bm1 << 1)
                    | ((unsigned)bm2 << 2) | ((unsigned)bm3 << 3);
        unsigned nn = (unsigned)bn0 | ((unsigned)bn1 << 1)
                    | ((unsigned)bn2 << 2) | ((unsigned)bn3 << 3);
        unsigned vm = nm << sh;
        unsigned vn = nn << sh;
        vm |= __shfl_xor_sync(0xffffffffu, vm, 1);
        vn |= __shfl_xor_sync(0xffffffffu, vn, 1);
        vm |= __shfl_xor_sync(0xffffffffu, vm, 2);
        vn |= __shfl_xor_sync(0xffffffffu, vn, 2);
        vm |= __shfl_xor_sync(0xffffffffu, vm, 4);
        vn |= __shfl_xor_sync(0xffffffffu, vn, 4);
        if ((lane & 7) == 0) {
            g_mask [(size_t)i*NW + k*4 + (lane>>3)] = vm;
            g_maskn[(size_t)i*NW + k*4 + (lane>>3)] = vn;
        }
    }
    float Sm = Sm0 + Sm1, Sn = Sn0 + Sn1;
    #pragma unroll
    for (int off = 16; off; off >>= 1) {
        Sm += __shfl_xor_sync(0xffffffffu, Sm, off);
        Sn += __shfl_xor_sync(0xffffffffu, Sn, off);
    }
    if (lane == 0) {
        g_km[i]  = (Sm > 0.f) ? 1.f / Sm : 0.f;
        g_kn[i]  = (Sn > 0.f) ? 1.f / Sn : 0.f;
        g_add[i] = ((Sm > 0.f) ? 0.f : INVN) + ((Sn > 0.f) ? 0.f : INVN);
        g_ep[i]  = ep;
        g_en[i]  = en;
    }
}

// ============================================================
// Kernel 3: fused attention + tf32 mma.sync (attn @ Wh)
// grid (KS, N/64); 128 thr = 4 warps x 16 rows  [R5 layout]
// ============================================================
__device__ __forceinline__ float attn_val(float Bj, float Dj,
        float ep, float en, float km, float kn, float add,
        unsigned mb, unsigned nb) {
    float ee = fmaxf(ep * Bj, en * Dj);          // exp(lrelu(wh1+wh2))
    float wsum = ((mb & 1u) ? km : 0.f) + ((nb & 1u) ? kn : 0.f);
    return fmaf(ee, wsum, add);
}

__global__ void __launch_bounds__(128, 4) k_main(float* __restrict__ attn) {
    __shared__ uint32_t whs[64*72];            // tf32 Wh tile, padded (18.4 KB)
    __shared__ float    at_s[64*68];           // attention tile [row][j] (17.4 KB)
    __shared__ float    Bs[64], Ds[64];

    int t = threadIdx.x, w = t >> 5, lane = t & 31;
    int g = lane >> 2, c = lane & 3;
    int i0 = blockIdx.y * 64;
    int rel0 = w*16 + g, rel1 = rel0 + 8;
    int r0 = i0 + rel0, r1 = i0 + rel1;

    float ep0 = g_ep[r0], en0 = g_en[r0], km0 = g_km[r0], kn0 = g_kn[r0], add0 = g_add[r0];
    float ep1 = g_ep[r1], en1 = g_en[r1], km1 = g_km[r1], kn1 = g_kn[r1], add1 = g_add[r1];

    float acc[8][4];
    #pragma unroll
    for (int nt = 0; nt < 8; nt++)
        #pragma unroll
        for (int q = 0; q < 4; q++) acc[nt][q] = 0.f;

    int jcta = blockIdx.x * (N/KS);

    for (int tt = 0; tt < (N/KS)/64; tt++) {
        int j0 = jcta + tt*64;
        __syncthreads();
        // stage Wh tile (64 j x 64 f) as tf32, row pad 72
        #pragma unroll
        for (int q = 0; q < 8; q++) {
            int idx = t + 128*q;
            int r = idx >> 4, c4 = (idx & 15) * 4;
            float4 v = *reinterpret_cast<const float4*>(&g_Wh[(size_t)(j0+r)*FO + c4]);
            uint32_t* p = &whs[r*72 + c4];
            p[0] = tf32bits(v.x); p[1] = tf32bits(v.y);
            p[2] = tf32bits(v.z); p[3] = tf32bits(v.w);
        }
        if (t < 64) { float2 bd = g_BD[j0+t]; Bs[t] = bd.x; Ds[t] = bd.y; }
        __syncthreads();

        int wb = j0 >> 5;
        uint2 mw0 = *reinterpret_cast<const uint2*>(&g_mask [(size_t)r0*NW + wb]);
        uint2 nw0 = *reinterpret_cast<const uint2*>(&g_maskn[(size_t)r0*NW + wb]);
        uint2 mw1 = *reinterpret_cast<const uint2*>(&g_mask [(size_t)r1*NW + wb]);
        uint2 nw1 = *reinterpret_cast<const uint2*>(&g_maskn[(size_t)r1*NW + wb]);

        #pragma unroll
        for (int kk = 0; kk < 8; kk++) {
            int jA = kk*8 + c, jB = jA + 4;
            float BA = Bs[jA], DA = Ds[jA];
            float BB = Bs[jB], DB = Ds[jB];
            unsigned m0 = (kk < 4) ? mw0.x : mw0.y;
            unsigned n0 = (kk < 4) ? nw0.x : nw0.y;
            unsigned m1 = (kk < 4) ? mw1.x : mw1.y;
            unsigned n1 = (kk < 4) ? nw1.x : nw1.y;
            int sA = (kk & 3)*8 + c, sB = sA + 4;

            float v00 = attn_val(BA, DA, ep0, en0, km0, kn0, add0, m0>>sA, n0>>sA);
            float v10 = attn_val(BA, DA, ep1, en1, km1, kn1, add1, m1>>sA, n1>>sA);
            float v01 = attn_val(BB, DB, ep0, en0, km0, kn0, add0, m0>>sB, n0>>sB);
            float v11 = attn_val(BB, DB, ep1, en1, km1, kn1, add1, m1>>sB, n1>>sB);

            // conflict-free STS (banks 4g+c+8kk all distinct within warp)
            at_s[rel0*68 + jA] = v00;  at_s[rel0*68 + jB] = v01;
            at_s[rel1*68 + jA] = v10;  at_s[rel1*68 + jB] = v11;

            uint32_t a0 = tf32bits(v00), a1 = tf32bits(v10);
            uint32_t a2 = tf32bits(v01), a3 = tf32bits(v11);

            int rowA = jA*72, rowB = jB*72;
            #pragma unroll
            for (int nt = 0; nt < 8; nt++) {
                uint32_t b0 = whs[rowA + nt*8 + g];
                uint32_t b1 = whs[rowB + nt*8 + g];
                mma_tf32(acc[nt], a0, a1, a2, a3, b0, b1);
            }
        }
        __syncthreads();

        // coalesced copy-out: 64x64 tile = 1024 float4, 8 per thread
        #pragma unroll
        for (int q = 0; q < 8; q++) {
            int idx = t + 128*q;
            int row = idx >> 4, c4 = (idx & 15) * 4;
            float4 v = *reinterpret_cast<const float4*>(&at_s[row*68 + c4]);
            *reinterpret_cast<float4*>(&attn[(size_t)(i0+row)*N + j0 + c4]) = v;
        }
    }

    #pragma unroll
    for (int nt = 0; nt < 8; nt++) {
        atomicAdd(&g_hp[(size_t)r0*FO + nt*8 + 2*c    ], acc[nt][0]);
        atomicAdd(&g_hp[(size_t)r0*FO + nt*8 + 2*c + 1], acc[nt][1]);
        atomicAdd(&g_hp[(size_t)r1*FO + nt*8 + 2*c    ], acc[nt][2]);
        atomicAdd(&g_hp[(size_t)r1*FO + nt*8 + 2*c + 1], acc[nt][3]);
    }
}

// ============================================================
// Kernel 4: out = elu(h_prime)
// ============================================================
__global__ void k_elu(float* __restrict__ out) {
    int tid = blockIdx.x * 256 + threadIdx.x;
    float x = g_hp[tid];
    out[tid] = x > 0.f ? x : expm1f(x);
}

// ============================================================
extern "C" void kernel_launch(void* const* d_in, const int* in_sizes, int n_in,
                              void* d_out, int out_size) {
    const float* h    = (const float*)d_in[0];
    const float* W    = (const float*)d_in[1];
    const float* a    = (const float*)d_in[2];
    const int*   adj  = (const int*)d_in[3];
    const int*   adjn = (const int*)d_in[4];

    float* out  = (float*)d_out;
    float* attn = out + (size_t)N * FO;

    k_gemm1<<<N/8, 512>>>(h, W, a);
    k_prep<<<N/256, 256>>>();
    k_spack<<<N/8, 256>>>(adj, adjn);
    k_main<<<dim3(KS, N/64), 128>>>(attn);
    k_elu<<<(N*FO)/256, 256>>>(out);
}

// round 8
// speedup vs baseline: 1.6338x; 1.1319x over previous
#include <cuda_runtime.h>
#include <cstdint>

#define N     8192
#define FIN   512
#define FO    64
#define NW    256
#define INVN  (1.0f/8192.0f)
#define KS    4

// ---- scratch ----
__device__ float    g_Wh[N*FO];
__device__ uint32_t g_Whtf[N*FO];     // tf32 bits of Wh
__device__ float    g_Wh1[N];
__device__ float    g_Wh2[N];
__device__ float2   g_BD[N];          // (exp(wh2), exp(0.2*wh2))
__device__ float    g_add[N];
__device__ float    g_ep[N], g_en[N];
__device__ float    g_km[N], g_kn[N];
__device__ unsigned g_mask[N*NW];
__device__ unsigned g_maskn[N*NW];
__device__ float    g_hp[N*FO];

__device__ __forceinline__ uint32_t tf32bits(float x) {
    uint32_t r; asm("cvt.rna.tf32.f32 %0, %1;" : "=r"(r) : "f"(x)); return r;
}
__device__ __forceinline__ uint32_t smem_u32(const void* p) {
    uint32_t a;
    asm("{ .reg .u64 t; cvta.to.shared.u64 t, %1; cvt.u32.u64 %0, t; }" : "=r"(a) : "l"(p));
    return a;
}
__device__ __forceinline__ void cp16(uint32_t dst, const void* src) {
    asm volatile("cp.async.ca.shared.global [%0], [%1], 16;" :: "r"(dst), "l"(src));
}
__device__ __forceinline__ void cp8(uint32_t dst, const void* src) {
    asm volatile("cp.async.ca.shared.global [%0], [%1], 8;" :: "r"(dst), "l"(src));
}
__device__ __forceinline__ void mma_tf32(float* d,
        uint32_t a0, uint32_t a1, uint32_t a2, uint32_t a3,
        uint32_t b0, uint32_t b1) {
    asm volatile("mma.sync.aligned.m16n8k8.row.col.f32.tf32.tf32.f32 "
        "{%0,%1,%2,%3}, {%4,%5,%6,%7}, {%8,%9}, {%0,%1,%2,%3};"
        : "+f"(d[0]), "+f"(d[1]), "+f"(d[2]), "+f"(d[3])
        : "r"(a0), "r"(a1), "r"(a2), "r"(a3), "r"(b0), "r"(b1));
}

// ============================================================
// Kernel 1: Wh = h @ W (smem-tiled). 128 thr, 32 rows/block.
// thread = 8 rows x 2 cols. Also writes tf32 copy.
// ============================================================
__global__ void __launch_bounds__(128) k_gemm1(const float* __restrict__ h,
                                               const float* __restrict__ W) {
    __shared__ float Ws[64*64];    // [kk][f], 16KB
    __shared__ float hs[32*64];    // [row][kk], 8KB

    int t = threadIdx.x;
    int f2 = t & 31, rg = t >> 5;          // 4 row-groups x 8 rows
    int i0 = blockIdx.x * 32;

    float acc[8][2];
    #pragma unroll
    for (int r = 0; r < 8; r++) { acc[r][0] = 0.f; acc[r][1] = 0.f; }

    for (int kt = 0; kt < 8; kt++) {
        __syncthreads();
        // stage W tile: 64x64 floats
        #pragma unroll
        for (int q = 0; q < 8; q++) {
            int idx = t + 128*q;
            int kk = idx >> 4, c4 = (idx & 15) * 4;
            *reinterpret_cast<float4*>(&Ws[kk*64 + c4]) =
                *reinterpret_cast<const float4*>(&W[(size_t)(kt*64 + kk)*FO + c4]);
        }
        // stage h tile: 32 rows x 64 k
        #pragma unroll
        for (int q = 0; q < 4; q++) {
            int idx = t + 128*q;
            int row = idx >> 4, c4 = (idx & 15) * 4;
            *reinterpret_cast<float4*>(&hs[row*64 + c4]) =
                *reinterpret_cast<const float4*>(&h[(size_t)(i0+row)*FIN + kt*64 + c4]);
        }
        __syncthreads();

        #pragma unroll 8
        for (int kk = 0; kk < 64; kk++) {
            float w0 = Ws[kk*64 + f2];
            float w1 = Ws[kk*64 + f2 + 32];
            #pragma unroll
            for (int r = 0; r < 8; r++) {
                float hv = hs[(rg*8 + r)*64 + kk];
                acc[r][0] = fmaf(hv, w0, acc[r][0]);
                acc[r][1] = fmaf(hv, w1, acc[r][1]);
            }
        }
    }

    #pragma unroll
    for (int r = 0; r < 8; r++) {
        size_t o = (size_t)(i0 + rg*8 + r) * FO;
        g_Wh[o + f2]        = acc[r][0];
        g_Wh[o + f2 + 32]   = acc[r][1];
        g_Whtf[o + f2]      = tf32bits(acc[r][0]);
        g_Whtf[o + f2 + 32] = tf32bits(acc[r][1]);
    }
}

// ============================================================
// Kernel 1b: Wh1 = Wh@a[:64], Wh2 = Wh@a[64:]; warp per row
// ============================================================
__global__ void k_wh12(const float* __restrict__ a) {
    __shared__ float a_s[2*FO];
    int t = threadIdx.x, lane = t & 31, w = t >> 5;
    a_s[t] = a[t];
    __syncthreads();
    int row = blockIdx.x * 4 + w;
    float2 v = reinterpret_cast<const float2*>(&g_Wh[(size_t)row*FO])[lane];
    float p1 = v.x * a_s[2*lane]      + v.y * a_s[2*lane + 1];
    float p2 = v.x * a_s[64 + 2*lane] + v.y * a_s[64 + 2*lane + 1];
    #pragma unroll
    for (int off = 16; off; off >>= 1) {
        p1 += __shfl_down_sync(0xffffffffu, p1, off);
        p2 += __shfl_down_sync(0xffffffffu, p2, off);
    }
    if (lane == 0) { g_Wh1[row] = p1; g_Wh2[row] = p2; }
}

// ============================================================
// Kernel 1c: BD[j] = (exp(wh2_j), exp(0.2 wh2_j))
// ============================================================
__global__ void k_prep() {
    int tid = blockIdx.x * 256 + threadIdx.x;
    float w2 = g_Wh2[tid];
    g_BD[tid] = make_float2(expf(w2), expf(0.2f * w2));
}

// ============================================================
// Kernel 2: FUSED adj pass: ballot-pack + softmax sums
// ============================================================
__global__ void k_spack(const int* __restrict__ adj,
                        const int* __restrict__ adjn) {
    int tid = blockIdx.x * 256 + threadIdx.x;
    g_hp[2*tid]     = 0.f;
    g_hp[2*tid + 1] = 0.f;

    int lane = threadIdx.x & 31;
    int i    = blockIdx.x * 8 + (threadIdx.x >> 5);
    float wh1 = g_Wh1[i];
    float ep = expf(wh1);
    float en = expf(0.2f * wh1);
    const int* arow = adj  + (size_t)i * N;
    const int* nrow = adjn + (size_t)i * N;
    int sh = (lane & 7) * 4;

    float Sm0 = 0.f, Sm1 = 0.f, Sn0 = 0.f, Sn1 = 0.f;

    #pragma unroll 2
    for (int k = 0; k < N/128; k++) {
        int jb = k*128 + lane*4;
        int4   av  = *reinterpret_cast<const int4*>(&arow[jb]);
        int4   nv  = *reinterpret_cast<const int4*>(&nrow[jb]);
        float4 bd0 = *reinterpret_cast<const float4*>(&g_BD[jb]);
        float4 bd1 = *reinterpret_cast<const float4*>(&g_BD[jb + 2]);

        float v0 = fmaxf(ep*bd0.x, en*bd0.y);
        float v1 = fmaxf(ep*bd0.z, en*bd0.w);
        float v2 = fmaxf(ep*bd1.x, en*bd1.y);
        float v3 = fmaxf(ep*bd1.z, en*bd1.w);

        bool bm0 = av.x > 0, bm1 = av.y > 0, bm2 = av.z > 0, bm3 = av.w > 0;
        bool bn0 = nv.x > 0, bn1 = nv.y > 0, bn2 = nv.z > 0, bn3 = nv.w > 0;

        if (bm0) Sm0 += v0;   if (bm1) Sm1 += v1;
        if (bm2) Sm0 += v2;   if (bm3) Sm1 += v3;
        if (bn0) Sn0 += v0;   if (bn1) Sn1 += v1;
        if (bn2) Sn0 += v2;   if (bn3) Sn1 += v3;

        unsigned nm = (unsigned)bm0 | ((unsigned)bm1 << 1)
                    | ((unsigned)bm2 << 2) | ((unsigned)bm3 << 3);
        unsigned nn = (unsigned)bn0 | ((unsigned)bn1 << 1)
                    | ((unsigned)bn2 << 2) | ((unsigned)bn3 << 3);
        unsigned vm = nm << sh;
        unsigned vn = nn << sh;
        vm |= __shfl_xor_sync(0xffffffffu, vm, 1);
        vn |= __shfl_xor_sync(0xffffffffu, vn, 1);
        vm |= __shfl_xor_sync(0xffffffffu, vm, 2);
        vn |= __shfl_xor_sync(0xffffffffu, vn, 2);
        vm |= __shfl_xor_sync(0xffffffffu, vm, 4);
        vn |= __shfl_xor_sync(0xffffffffu, vn, 4);
        if ((lane & 7) == 0) {
            g_mask [(size_t)i*NW + k*4 + (lane>>3)] = vm;
            g_maskn[(size_t)i*NW + k*4 + (lane>>3)] = vn;
        }
    }
    float Sm = Sm0 + Sm1, Sn = Sn0 + Sn1;
    #pragma unroll
    for (int off = 16; off; off >>= 1) {
        Sm += __shfl_xor_sync(0xffffffffu, Sm, off);
        Sn += __shfl_xor_sync(0xffffffffu, Sn, off);
    }
    if (lane == 0) {
        g_km[i]  = (Sm > 0.f) ? 1.f / Sm : 0.f;
        g_kn[i]  = (Sn > 0.f) ? 1.f / Sn : 0.f;
        g_add[i] = ((Sm > 0.f) ? 0.f : INVN) + ((Sn > 0.f) ? 0.f : INVN);
        g_ep[i]  = ep;
        g_en[i]  = en;
    }
}

// ============================================================
// Kernel 3: fused attention + tf32 mma, cp.async double-buffer
// grid (KS, N/64); 128 thr = 4 warps x 16 rows
// smem: whs x2 (18432 ea) | at_s (17408) | BD x2 (512 ea) = 55296
// ============================================================
#define WHS_SZ  18432
#define AT_OFF  36864
#define BD_OFF  54272
#define SMEM_SZ 55296
#define TL      ((N/KS)/64)

__device__ __forceinline__ float attn_val(float Bj, float Dj,
        float ep, float en, float km, float kn, float add,
        unsigned mb, unsigned nb) {
    float ee = fmaxf(ep * Bj, en * Dj);
    float wsum = ((mb & 1u) ? km : 0.f) + ((nb & 1u) ? kn : 0.f);
    return fmaf(ee, wsum, add);
}

__global__ void __launch_bounds__(128, 4) k_main(float* __restrict__ attn) {
    extern __shared__ char sm[];
    uint32_t sb = smem_u32(sm);

    int t = threadIdx.x, w = t >> 5, lane = t & 31;
    int g = lane >> 2, c = lane & 3;
    int i0 = blockIdx.y * 64;
    int rel0 = w*16 + g, rel1 = rel0 + 8;
    int r0 = i0 + rel0, r1 = i0 + rel1;
    int jcta = blockIdx.x * (N/KS);

    float ep0 = g_ep[r0], en0 = g_en[r0], km0 = g_km[r0], kn0 = g_kn[r0], add0 = g_add[r0];
    float ep1 = g_ep[r1], en1 = g_en[r1], km1 = g_km[r1], kn1 = g_kn[r1], add1 = g_add[r1];

    float acc[8][4];
    #pragma unroll
    for (int nt = 0; nt < 8; nt++)
        #pragma unroll
        for (int q = 0; q < 4; q++) acc[nt][q] = 0.f;

    float* at_s = reinterpret_cast<float*>(sm + AT_OFF);

    // ---- stage tile 0 ----
    {
        int j0 = jcta;
        #pragma unroll
        for (int q = 0; q < 8; q++) {
            int idx = t + 128*q;
            int r = idx >> 4, c4 = (idx & 15) * 4;
            cp16(sb + (r*72 + c4)*4, &g_Whtf[(size_t)(j0+r)*FO + c4]);
        }
        if (t < 64) cp8(sb + BD_OFF + t*8, &g_BD[j0 + t]);
        asm volatile("cp.async.commit_group;" ::: "memory");
    }

    for (int tt = 0; tt < TL; tt++) {
        int buf = tt & 1;
        int j0  = jcta + tt*64;

        if (tt + 1 < TL) {
            int nb_ = (tt+1) & 1;
            int jn  = j0 + 64;
            #pragma unroll
            for (int q = 0; q < 8; q++) {
                int idx = t + 128*q;
                int r = idx >> 4, c4 = (idx & 15) * 4;
                cp16(sb + nb_*WHS_SZ + (r*72 + c4)*4, &g_Whtf[(size_t)(jn+r)*FO + c4]);
            }
            if (t < 64) cp8(sb + BD_OFF + nb_*512 + t*8, &g_BD[jn + t]);
            asm volatile("cp.async.commit_group;" ::: "memory");
            asm volatile("cp.async.wait_group 1;" ::: "memory");
        } else {
            asm volatile("cp.async.wait_group 0;" ::: "memory");
        }
        __syncthreads();

        const uint32_t* whs = reinterpret_cast<const uint32_t*>(sm + buf*WHS_SZ);
        const float2*   BDs = reinterpret_cast<const float2*>(sm + BD_OFF + buf*512);

        int wb = j0 >> 5;
        uint2 mw0 = *reinterpret_cast<const uint2*>(&g_mask [(size_t)r0*NW + wb]);
        uint2 nw0 = *reinterpret_cast<const uint2*>(&g_maskn[(size_t)r0*NW + wb]);
        uint2 mw1 = *reinterpret_cast<const uint2*>(&g_mask [(size_t)r1*NW + wb]);
        uint2 nw1 = *reinterpret_cast<const uint2*>(&g_maskn[(size_t)r1*NW + wb]);

        #pragma unroll
        for (int kk = 0; kk < 8; kk++) {
            int jA = kk*8 + c, jB = jA + 4;
            float2 bdA = BDs[jA];
            float2 bdB = BDs[jB];
            unsigned m0 = (kk < 4) ? mw0.x : mw0.y;
            unsigned n0 = (kk < 4) ? nw0.x : nw0.y;
            unsigned m1 = (kk < 4) ? mw1.x : mw1.y;
            unsigned n1 = (kk < 4) ? nw1.x : nw1.y;
            int sA = (kk & 3)*8 + c, sB = sA + 4;

            float v00 = attn_val(bdA.x, bdA.y, ep0, en0, km0, kn0, add0, m0>>sA, n0>>sA);
            float v10 = attn_val(bdA.x, bdA.y, ep1, en1, km1, kn1, add1, m1>>sA, n1>>sA);
            float v01 = attn_val(bdB.x, bdB.y, ep0, en0, km0, kn0, add0, m0>>sB, n0>>sB);
            float v11 = attn_val(bdB.x, bdB.y, ep1, en1, km1, kn1, add1, m1>>sB, n1>>sB);

            at_s[rel0*68 + jA] = v00;  at_s[rel0*68 + jB] = v01;
            at_s[rel1*68 + jA] = v10;  at_s[rel1*68 + jB] = v11;

            uint32_t a0 = tf32bits(v00), a1 = tf32bits(v10);
            uint32_t a2 = tf32bits(v01), a3 = tf32bits(v11);

            int rowA = jA*72, rowB = jB*72;
            #pragma unroll
            for (int nt = 0; nt < 8; nt++) {
                uint32_t b0 = whs[rowA + nt*8 + g];
                uint32_t b1 = whs[rowB + nt*8 + g];
                mma_tf32(acc[nt], a0, a1, a2, a3, b0, b1);
            }
        }
        __syncthreads();

        // copy-out: 2 rows per warp-inst -> 256B contiguous segments
        #pragma unroll
        for (int q = 0; q < 8; q++) {
            int row = (t >> 4) + 8*q;
            int c4  = (t & 15) * 4;
            float4 v = *reinterpret_cast<const float4*>(&at_s[row*68 + c4]);
            *reinterpret_cast<float4*>(&attn[(size_t)(i0+row)*N + j0 + c4]) = v;
        }
    }

    #pragma unroll
    for (int nt = 0; nt < 8; nt++) {
        atomicAdd(&g_hp[(size_t)r0*FO + nt*8 + 2*c    ], acc[nt][0]);
        atomicAdd(&g_hp[(size_t)r0*FO + nt*8 + 2*c + 1], acc[nt][1]);
        atomicAdd(&g_hp[(size_t)r1*FO + nt*8 + 2*c    ], acc[nt][2]);
        atomicAdd(&g_hp[(size_t)r1*FO + nt*8 + 2*c + 1], acc[nt][3]);
    }
}

// ============================================================
// Kernel 4: out = elu(h_prime)
// ============================================================
__global__ void k_elu(float* __restrict__ out) {
    int tid = blockIdx.x * 256 + threadIdx.x;
    float x = g_hp[tid];
    out[tid] = x > 0.f ? x : expm1f(x);
}

// ============================================================
extern "C" void kernel_launch(void* const* d_in, const int* in_sizes, int n_in,
                              void* d_out, int out_size) {
    const float* h    = (const float*)d_in[0];
    const float* W    = (const float*)d_in[1];
    const float* a    = (const float*)d_in[2];
    const int*   adj  = (const int*)d_in[3];
    const int*   adjn = (const int*)d_in[4];

    float* out  = (float*)d_out;
    float* attn = out + (size_t)N * FO;

    cudaFuncSetAttribute(k_main, cudaFuncAttributeMaxDynamicSharedMemorySize, SMEM_SZ);

    k_gemm1<<<N/32, 128>>>(h, W);
    k_wh12<<<N/4, 128>>>(a);
    k_prep<<<N/256, 256>>>();
    k_spack<<<N/8, 256>>>(adj, adjn);
    k_main<<<dim3(KS, N/64), 128, SMEM_SZ>>>(attn);
    k_elu<<<(N*FO)/256, 256>>>(out);
}

// round 9
// speedup vs baseline: 1.8064x; 1.1056x over previous
#include <cuda_runtime.h>
#include <cstdint>

#define N     8192
#define FIN   512
#define FO    64
#define NW    256
#define INVN  (1.0f/8192.0f)
#define KS    4

// ---- scratch ----
__device__ float    g_Wh[N*FO];
__device__ uint32_t g_Whtf[N*FO];     // tf32 bits of Wh
__device__ float    g_Wh1[N];
__device__ float2   g_BD[N];          // (exp(wh2), exp(0.2*wh2))
__device__ float    g_add[N];
__device__ float    g_ep[N], g_en[N];
__device__ float    g_km[N], g_kn[N];
__device__ unsigned g_mask[N*NW];
__device__ unsigned g_maskn[N*NW];
__device__ float    g_hp[N*FO];

__device__ __forceinline__ uint32_t tf32bits(float x) {
    uint32_t r; asm("cvt.rna.tf32.f32 %0, %1;" : "=r"(r) : "f"(x)); return r;
}
__device__ __forceinline__ uint32_t smem_u32(const void* p) {
    uint32_t a;
    asm("{ .reg .u64 t; cvta.to.shared.u64 t, %1; cvt.u32.u64 %0, t; }" : "=r"(a) : "l"(p));
    return a;
}
__device__ __forceinline__ void cp16(uint32_t dst, const void* src) {
    asm volatile("cp.async.ca.shared.global [%0], [%1], 16;" :: "r"(dst), "l"(src));
}
__device__ __forceinline__ void cp8(uint32_t dst, const void* src) {
    asm volatile("cp.async.ca.shared.global [%0], [%1], 8;" :: "r"(dst), "l"(src));
}
__device__ __forceinline__ void mma_tf32(float* d,
        uint32_t a0, uint32_t a1, uint32_t a2, uint32_t a3,
        uint32_t b0, uint32_t b1) {
    asm volatile("mma.sync.aligned.m16n8k8.row.col.f32.tf32.tf32.f32 "
        "{%0,%1,%2,%3}, {%4,%5,%6,%7}, {%8,%9}, {%0,%1,%2,%3};"
        : "+f"(d[0]), "+f"(d[1]), "+f"(d[2]), "+f"(d[3])
        : "r"(a0), "r"(a1), "r"(a2), "r"(a3), "r"(b0), "r"(b1));
}
__device__ __forceinline__ int4 ldcs4(const int* p) {
    int4 v;
    asm volatile("ld.global.cs.v4.s32 {%0,%1,%2,%3}, [%4];"
        : "=r"(v.x), "=r"(v.y), "=r"(v.z), "=r"(v.w) : "l"(p));
    return v;
}

// ============================================================
// Kernel 1: Wh = h @ W (smem-tiled) + fused Wh1/Wh2/BD epilogue
// 128 thr, 32 rows/block; thread = 8 rows x 2 cols.
// ============================================================
__global__ void __launch_bounds__(128) k_gemm1(const float* __restrict__ h,
                                               const float* __restrict__ W,
                                               const float* __restrict__ a) {
    __shared__ float Ws[64*64];    // 16KB
    __shared__ float hs[32*64];    // 8KB
    __shared__ float a_s[2*FO];

    int t = threadIdx.x;
    int f2 = t & 31, rg = t >> 5;
    int i0 = blockIdx.x * 32;
    if (t < 2*FO) a_s[t] = a[t];

    float acc[8][2];
    #pragma unroll
    for (int r = 0; r < 8; r++) { acc[r][0] = 0.f; acc[r][1] = 0.f; }

    for (int kt = 0; kt < 8; kt++) {
        __syncthreads();
        #pragma unroll
        for (int q = 0; q < 8; q++) {
            int idx = t + 128*q;
            int kk = idx >> 4, c4 = (idx & 15) * 4;
            *reinterpret_cast<float4*>(&Ws[kk*64 + c4]) =
                *reinterpret_cast<const float4*>(&W[(size_t)(kt*64 + kk)*FO + c4]);
        }
        #pragma unroll
        for (int q = 0; q < 4; q++) {
            int idx = t + 128*q;
            int row = idx >> 4, c4 = (idx & 15) * 4;
            *reinterpret_cast<float4*>(&hs[row*64 + c4]) =
                *reinterpret_cast<const float4*>(&h[(size_t)(i0+row)*FIN + kt*64 + c4]);
        }
        __syncthreads();

        #pragma unroll 8
        for (int kk = 0; kk < 64; kk++) {
            float w0 = Ws[kk*64 + f2];
            float w1 = Ws[kk*64 + f2 + 32];
            #pragma unroll
            for (int r = 0; r < 8; r++) {
                float hv = hs[(rg*8 + r)*64 + kk];
                acc[r][0] = fmaf(hv, w0, acc[r][0]);
                acc[r][1] = fmaf(hv, w1, acc[r][1]);
            }
        }
    }

    // write Wh + tf32 copy; fused Wh1/Wh2/BD epilogue
    #pragma unroll
    for (int r = 0; r < 8; r++) {
        size_t o = (size_t)(i0 + rg*8 + r) * FO;
        g_Wh[o + f2]        = acc[r][0];
        g_Wh[o + f2 + 32]   = acc[r][1];
        g_Whtf[o + f2]      = tf32bits(acc[r][0]);
        g_Whtf[o + f2 + 32] = tf32bits(acc[r][1]);

        float p1 = acc[r][0] * a_s[f2] + acc[r][1] * a_s[f2 + 32];
        float p2 = acc[r][0] * a_s[64 + f2] + acc[r][1] * a_s[96 + f2];
        #pragma unroll
        for (int off = 16; off; off >>= 1) {
            p1 += __shfl_down_sync(0xffffffffu, p1, off);
            p2 += __shfl_down_sync(0xffffffffu, p2, off);
        }
        if (f2 == 0) {
            int row = i0 + rg*8 + r;
            g_Wh1[row] = p1;
            g_BD[row]  = make_float2(expf(p2), expf(0.2f * p2));
        }
    }
}

// ============================================================
// Kernel 2: FUSED adj pass: ballot-pack + softmax sums
// streaming loads + unroll 4 for MLP
// ============================================================
__global__ void k_spack(const int* __restrict__ adj,
                        const int* __restrict__ adjn) {
    int tid = blockIdx.x * 256 + threadIdx.x;
    g_hp[2*tid]     = 0.f;
    g_hp[2*tid + 1] = 0.f;

    int lane = threadIdx.x & 31;
    int i    = blockIdx.x * 8 + (threadIdx.x >> 5);
    float wh1 = g_Wh1[i];
    float ep = expf(wh1);
    float en = expf(0.2f * wh1);
    const int* arow = adj  + (size_t)i * N;
    const int* nrow = adjn + (size_t)i * N;
    int sh = (lane & 7) * 4;

    float Sm0 = 0.f, Sm1 = 0.f, Sn0 = 0.f, Sn1 = 0.f;

    #pragma unroll 4
    for (int k = 0; k < N/128; k++) {
        int jb = k*128 + lane*4;
        int4   av  = ldcs4(&arow[jb]);
        int4   nv  = ldcs4(&nrow[jb]);
        float4 bd0 = *reinterpret_cast<const float4*>(&g_BD[jb]);
        float4 bd1 = *reinterpret_cast<const float4*>(&g_BD[jb + 2]);

        float v0 = fmaxf(ep*bd0.x, en*bd0.y);
        float v1 = fmaxf(ep*bd0.z, en*bd0.w);
        float v2 = fmaxf(ep*bd1.x, en*bd1.y);
        float v3 = fmaxf(ep*bd1.z, en*bd1.w);

        bool bm0 = av.x > 0, bm1 = av.y > 0, bm2 = av.z > 0, bm3 = av.w > 0;
        bool bn0 = nv.x > 0, bn1 = nv.y > 0, bn2 = nv.z > 0, bn3 = nv.w > 0;

        if (bm0) Sm0 += v0;   if (bm1) Sm1 += v1;
        if (bm2) Sm0 += v2;   if (bm3) Sm1 += v3;
        if (bn0) Sn0 += v0;   if (bn1) Sn1 += v1;
        if (bn2) Sn0 += v2;   if (bn3) Sn1 += v3;

        unsigned nm = (unsigned)bm0 | ((unsigned)bm1 << 1)
                    | ((unsigned)bm2 << 2) | ((unsigned)bm3 << 3);
        unsigned nn = (unsigned)bn0 | ((unsigned)bn1 << 1)
                    | ((unsigned)bn2 << 2) | ((unsigned)bn3 << 3);
        unsigned vm = nm << sh;
        unsigned vn = nn << sh;
        vm |= __shfl_xor_sync(0xffffffffu, vm, 1);
        vn |= __shfl_xor_sync(0xffffffffu, vn, 1);
        vm |= __shfl_xor_sync(0xffffffffu, vm, 2);
        vn |= __shfl_xor_sync(0xffffffffu, vn, 2);
        vm |= __shfl_xor_sync(0xffffffffu, vm, 4);
        vn |= __shfl_xor_sync(0xffffffffu, vn, 4);
        if ((lane & 7) == 0) {
            g_mask [(size_t)i*NW + k*4 + (lane>>3)] = vm;
            g_maskn[(size_t)i*NW + k*4 + (lane>>3)] = vn;
        }
    }
    float Sm = Sm0 + Sm1, Sn = Sn0 + Sn1;
    #pragma unroll
    for (int off = 16; off; off >>= 1) {
        Sm += __shfl_xor_sync(0xffffffffu, Sm, off);
        Sn += __shfl_xor_sync(0xffffffffu, Sn, off);
    }
    if (lane == 0) {
        g_km[i]  = (Sm > 0.f) ? 1.f / Sm : 0.f;
        g_kn[i]  = (Sn > 0.f) ? 1.f / Sn : 0.f;
        g_add[i] = ((Sm > 0.f) ? 0.f : INVN) + ((Sn > 0.f) ? 0.f : INVN);
        g_ep[i]  = ep;
        g_en[i]  = en;
    }
}

// ============================================================
// Kernel 3: fused attention + tf32 mma, cp.async double-buffer
// grid (KS, N/64); 128 thr = 4 warps x 16 rows
// ============================================================
#define WHS_SZ  18432
#define AT_OFF  36864
#define BD_OFF  54272
#define SMEM_SZ 55296
#define TL      ((N/KS)/64)

__device__ __forceinline__ float attn_val(float Bj, float Dj,
        float ep, float en, float km, float kn, float add,
        unsigned mb, unsigned nb) {
    float ee = fmaxf(ep * Bj, en * Dj);
    float wsum = ((mb & 1u) ? km : 0.f) + ((nb & 1u) ? kn : 0.f);
    return fmaf(ee, wsum, add);
}

__global__ void __launch_bounds__(128, 4) k_main(float* __restrict__ attn) {
    extern __shared__ char sm[];
    uint32_t sb = smem_u32(sm);

    int t = threadIdx.x, w = t >> 5, lane = t & 31;
    int g = lane >> 2, c = lane & 3;
    int i0 = blockIdx.y * 64;
    int rel0 = w*16 + g, rel1 = rel0 + 8;
    int r0 = i0 + rel0, r1 = i0 + rel1;
    int jcta = blockIdx.x * (N/KS);

    float ep0 = g_ep[r0], en0 = g_en[r0], km0 = g_km[r0], kn0 = g_kn[r0], add0 = g_add[r0];
    float ep1 = g_ep[r1], en1 = g_en[r1], km1 = g_km[r1], kn1 = g_kn[r1], add1 = g_add[r1];

    float acc[8][4];
    #pragma unroll
    for (int nt = 0; nt < 8; nt++)
        #pragma unroll
        for (int q = 0; q < 4; q++) acc[nt][q] = 0.f;

    float* at_s = reinterpret_cast<float*>(sm + AT_OFF);

    {
        int j0 = jcta;
        #pragma unroll
        for (int q = 0; q < 8; q++) {
            int idx = t + 128*q;
            int r = idx >> 4, c4 = (idx & 15) * 4;
            cp16(sb + (r*72 + c4)*4, &g_Whtf[(size_t)(j0+r)*FO + c4]);
        }
        if (t < 64) cp8(sb + BD_OFF + t*8, &g_BD[j0 + t]);
        asm volatile("cp.async.commit_group;" ::: "memory");
    }

    for (int tt = 0; tt < TL; tt++) {
        int buf = tt & 1;
        int j0  = jcta + tt*64;

        if (tt + 1 < TL) {
            int nb_ = (tt+1) & 1;
            int jn  = j0 + 64;
            #pragma unroll
            for (int q = 0; q < 8; q++) {
                int idx = t + 128*q;
                int r = idx >> 4, c4 = (idx & 15) * 4;
                cp16(sb + nb_*WHS_SZ + (r*72 + c4)*4, &g_Whtf[(size_t)(jn+r)*FO + c4]);
            }
            if (t < 64) cp8(sb + BD_OFF + nb_*512 + t*8, &g_BD[jn + t]);
            asm volatile("cp.async.commit_group;" ::: "memory");
            asm volatile("cp.async.wait_group 1;" ::: "memory");
        } else {
            asm volatile("cp.async.wait_group 0;" ::: "memory");
        }
        __syncthreads();

        const uint32_t* whs = reinterpret_cast<const uint32_t*>(sm + buf*WHS_SZ);
        const float2*   BDs = reinterpret_cast<const float2*>(sm + BD_OFF + buf*512);

        int wb = j0 >> 5;
        uint2 mw0 = *reinterpret_cast<const uint2*>(&g_mask [(size_t)r0*NW + wb]);
        uint2 nw0 = *reinterpret_cast<const uint2*>(&g_maskn[(size_t)r0*NW + wb]);
        uint2 mw1 = *reinterpret_cast<const uint2*>(&g_mask [(size_t)r1*NW + wb]);
        uint2 nw1 = *reinterpret_cast<const uint2*>(&g_maskn[(size_t)r1*NW + wb]);

        #pragma unroll
        for (int kk = 0; kk < 8; kk++) {
            int jA = kk*8 + c, jB = jA + 4;
            float2 bdA = BDs[jA];
            float2 bdB = BDs[jB];
            unsigned m0 = (kk < 4) ? mw0.x : mw0.y;
            unsigned n0 = (kk < 4) ? nw0.x : nw0.y;
            unsigned m1 = (kk < 4) ? mw1.x : mw1.y;
            unsigned n1 = (kk < 4) ? nw1.x : nw1.y;
            int sA = (kk & 3)*8 + c, sB = sA + 4;

            float v00 = attn_val(bdA.x, bdA.y, ep0, en0, km0, kn0, add0, m0>>sA, n0>>sA);
            float v10 = attn_val(bdA.x, bdA.y, ep1, en1, km1, kn1, add1, m1>>sA, n1>>sA);
            float v01 = attn_val(bdB.x, bdB.y, ep0, en0, km0, kn0, add0, m0>>sB, n0>>sB);
            float v11 = attn_val(bdB.x, bdB.y, ep1, en1, km1, kn1, add1, m1>>sB, n1>>sB);

            at_s[rel0*68 + jA] = v00;  at_s[rel0*68 + jB] = v01;
            at_s[rel1*68 + jA] = v10;  at_s[rel1*68 + jB] = v11;

            uint32_t a0 = tf32bits(v00), a1 = tf32bits(v10);
            uint32_t a2 = tf32bits(v01), a3 = tf32bits(v11);

            int rowA = jA*72, rowB = jB*72;
            #pragma unroll
            for (int nt = 0; nt < 8; nt++) {
                uint32_t b0 = whs[rowA + nt*8 + g];
                uint32_t b1 = whs[rowB + nt*8 + g];
                mma_tf32(acc[nt], a0, a1, a2, a3, b0, b1);
            }
        }
        __syncthreads();

        #pragma unroll
        for (int q = 0; q < 8; q++) {
            int row = (t >> 4) + 8*q;
            int c4  = (t & 15) * 4;
            float4 v = *reinterpret_cast<const float4*>(&at_s[row*68 + c4]);
            *reinterpret_cast<float4*>(&attn[(size_t)(i0+row)*N + j0 + c4]) = v;
        }
    }

    #pragma unroll
    for (int nt = 0; nt < 8; nt++) {
        atomicAdd(&g_hp[(size_t)r0*FO + nt*8 + 2*c    ], acc[nt][0]);
        atomicAdd(&g_hp[(size_t)r0*FO + nt*8 + 2*c + 1], acc[nt][1]);
        atomicAdd(&g_hp[(size_t)r1*FO + nt*8 + 2*c    ], acc[nt][2]);
        atomicAdd(&g_hp[(size_t)r1*FO + nt*8 + 2*c + 1], acc[nt][3]);
    }
}

// ============================================================
// Kernel 4: out = elu(h_prime)
// ============================================================
__global__ void k_elu(float* __restrict__ out) {
    int tid = blockIdx.x * 256 + threadIdx.x;
    float x = g_hp[tid];
    out[tid] = x > 0.f ? x : expm1f(x);
}

// ============================================================
extern "C" void kernel_launch(void* const* d_in, const int* in_sizes, int n_in,
                              void* d_out, int out_size) {
    const float* h    = (const float*)d_in[0];
    const float* W    = (const float*)d_in[1];
    const float* a    = (const float*)d_in[2];
    const int*   adj  = (const int*)d_in[3];
    const int*   adjn = (const int*)d_in[4];

    float* out  = (float*)d_out;
    float* attn = out + (size_t)N * FO;

    cudaFuncSetAttribute(k_main, cudaFuncAttributeMaxDynamicSharedMemorySize, SMEM_SZ);

    k_gemm1<<<N/32, 128>>>(h, W, a);
    k_spack<<<N/8, 256>>>(adj, adjn);
    k_main<<<dim3(KS, N/64), 128, SMEM_SZ>>>(attn);
    k_elu<<<(N*FO)/256, 256>>>(out);
}

// round 10
// speedup vs baseline: 1.8070x; 1.0003x over previous
#include <cuda_runtime.h>
#include <cstdint>

#define N     8192
#define FIN   512
#define FO    64
#define NW    256
#define INVN  (1.0f/8192.0f)
#define KS    4

// ---- scratch ----
__device__ uint2    g_Whp[N*32];      // pair-packed tf32 Wh: [jblk][f][pairidx]
__device__ float    g_Wh1[N];
__device__ float2   g_BD[N];          // (exp(wh2), exp(0.2*wh2))
__device__ float    g_add[N];
__device__ float    g_ep[N], g_en[N];
__device__ float    g_km[N], g_kn[N];
__device__ unsigned g_mask[N*NW];
__device__ unsigned g_maskn[N*NW];
__device__ float    g_hp[N*FO];

__device__ __forceinline__ uint32_t tf32bits(float x) {
    uint32_t r; asm("cvt.rna.tf32.f32 %0, %1;" : "=r"(r) : "f"(x)); return r;
}
__device__ __forceinline__ uint32_t smem_u32(const void* p) {
    uint32_t a;
    asm("{ .reg .u64 t; cvta.to.shared.u64 t, %1; cvt.u32.u64 %0, t; }" : "=r"(a) : "l"(p));
    return a;
}
__device__ __forceinline__ void cp16(uint32_t dst, const void* src) {
    asm volatile("cp.async.ca.shared.global [%0], [%1], 16;" :: "r"(dst), "l"(src));
}
__device__ __forceinline__ void cp8(uint32_t dst, const void* src) {
    asm volatile("cp.async.ca.shared.global [%0], [%1], 8;" :: "r"(dst), "l"(src));
}
__device__ __forceinline__ void mma_tf32(float* d,
        uint32_t a0, uint32_t a1, uint32_t a2, uint32_t a3,
        uint32_t b0, uint32_t b1) {
    asm volatile("mma.sync.aligned.m16n8k8.row.col.f32.tf32.tf32.f32 "
        "{%0,%1,%2,%3}, {%4,%5,%6,%7}, {%8,%9}, {%0,%1,%2,%3};"
        : "+f"(d[0]), "+f"(d[1]), "+f"(d[2]), "+f"(d[3])
        : "r"(a0), "r"(a1), "r"(a2), "r"(a3), "r"(b0), "r"(b1));
}
__device__ __forceinline__ int4 ldcs4(const int* p) {
    int4 v;
    asm volatile("ld.global.cs.v4.s32 {%0,%1,%2,%3}, [%4];"
        : "=r"(v.x), "=r"(v.y), "=r"(v.z), "=r"(v.w) : "l"(p));
    return v;
}

// ============================================================
// Kernel 1: Wh = h @ W (smem-tiled) + fused Wh1/Wh2/BD epilogue
// + pair-packed tf32 output g_Whp
// 128 thr, 32 rows/block; thread = 8 rows x 2 cols.
// ============================================================
__global__ void __launch_bounds__(128) k_gemm1(const float* __restrict__ h,
                                               const float* __restrict__ W,
                                               const float* __restrict__ a) {
    __shared__ float Ws[64*64];    // 16KB
    __shared__ float hs[32*64];    // 8KB
    __shared__ float a_s[2*FO];

    int t = threadIdx.x;
    int f2 = t & 31, rg = t >> 5;
    int i0 = blockIdx.x * 32;
    if (t < 2*FO) a_s[t] = a[t];

    float acc[8][2];
    #pragma unroll
    for (int r = 0; r < 8; r++) { acc[r][0] = 0.f; acc[r][1] = 0.f; }

    for (int kt = 0; kt < 8; kt++) {
        __syncthreads();
        #pragma unroll
        for (int q = 0; q < 8; q++) {
            int idx = t + 128*q;
            int kk = idx >> 4, c4 = (idx & 15) * 4;
            *reinterpret_cast<float4*>(&Ws[kk*64 + c4]) =
                *reinterpret_cast<const float4*>(&W[(size_t)(kt*64 + kk)*FO + c4]);
        }
        #pragma unroll
        for (int q = 0; q < 4; q++) {
            int idx = t + 128*q;
            int row = idx >> 4, c4 = (idx & 15) * 4;
            *reinterpret_cast<float4*>(&hs[row*64 + c4]) =
                *reinterpret_cast<const float4*>(&h[(size_t)(i0+row)*FIN + kt*64 + c4]);
        }
        __syncthreads();

        #pragma unroll 8
        for (int kk = 0; kk < 64; kk++) {
            float w0 = Ws[kk*64 + f2];
            float w1 = Ws[kk*64 + f2 + 32];
            #pragma unroll
            for (int r = 0; r < 8; r++) {
                float hv = hs[(rg*8 + r)*64 + kk];
                acc[r][0] = fmaf(hv, w0, acc[r][0]);
                acc[r][1] = fmaf(hv, w1, acc[r][1]);
            }
        }
    }

    // pair-packed tf32 output: pairs (row jl, jl+4) at [b][col][idx]
    {
        int b = i0 >> 6;
        int jl_base = (i0 & 32) + rg*8;
        int idx0 = (jl_base >> 3) * 4;
        #pragma unroll
        for (int r = 0; r < 4; r++) {
            int idx = idx0 + r;
            g_Whp[(size_t)(b*64 + f2)*32 + idx] =
                make_uint2(tf32bits(acc[r][0]), tf32bits(acc[r+4][0]));
            g_Whp[(size_t)(b*64 + f2 + 32)*32 + idx] =
                make_uint2(tf32bits(acc[r][1]), tf32bits(acc[r+4][1]));
        }
    }

    // fused Wh1/Wh2/BD epilogue
    #pragma unroll
    for (int r = 0; r < 8; r++) {
        float p1 = acc[r][0] * a_s[f2] + acc[r][1] * a_s[f2 + 32];
        float p2 = acc[r][0] * a_s[64 + f2] + acc[r][1] * a_s[96 + f2];
        #pragma unroll
        for (int off = 16; off; off >>= 1) {
            p1 += __shfl_down_sync(0xffffffffu, p1, off);
            p2 += __shfl_down_sync(0xffffffffu, p2, off);
        }
        if (f2 == 0) {
            int row = i0 + rg*8 + r;
            g_Wh1[row] = p1;
            g_BD[row]  = make_float2(expf(p2), expf(0.2f * p2));
        }
    }
}

// ============================================================
// Kernel 2: FUSED adj pass: ballot-pack + softmax sums
// ============================================================
__global__ void k_spack(const int* __restrict__ adj,
                        const int* __restrict__ adjn) {
    int tid = blockIdx.x * 256 + threadIdx.x;
    g_hp[2*tid]     = 0.f;
    g_hp[2*tid + 1] = 0.f;

    int lane = threadIdx.x & 31;
    int i    = blockIdx.x * 8 + (threadIdx.x >> 5);
    float wh1 = g_Wh1[i];
    float ep = expf(wh1);
    float en = expf(0.2f * wh1);
    const int* arow = adj  + (size_t)i * N;
    const int* nrow = adjn + (size_t)i * N;
    int sh = (lane & 7) * 4;

    float Sm0 = 0.f, Sm1 = 0.f, Sn0 = 0.f, Sn1 = 0.f;

    #pragma unroll 4
    for (int k = 0; k < N/128; k++) {
        int jb = k*128 + lane*4;
        int4   av  = ldcs4(&arow[jb]);
        int4   nv  = ldcs4(&nrow[jb]);
        float4 bd0 = *reinterpret_cast<const float4*>(&g_BD[jb]);
        float4 bd1 = *reinterpret_cast<const float4*>(&g_BD[jb + 2]);

        float v0 = fmaxf(ep*bd0.x, en*bd0.y);
        float v1 = fmaxf(ep*bd0.z, en*bd0.w);
        float v2 = fmaxf(ep*bd1.x, en*bd1.y);
        float v3 = fmaxf(ep*bd1.z, en*bd1.w);

        bool bm0 = av.x > 0, bm1 = av.y > 0, bm2 = av.z > 0, bm3 = av.w > 0;
        bool bn0 = nv.x > 0, bn1 = nv.y > 0, bn2 = nv.z > 0, bn3 = nv.w > 0;

        if (bm0) Sm0 += v0;   if (bm1) Sm1 += v1;
        if (bm2) Sm0 += v2;   if (bm3) Sm1 += v3;
        if (bn0) Sn0 += v0;   if (bn1) Sn1 += v1;
        if (bn2) Sn0 += v2;   if (bn3) Sn1 += v3;

        unsigned nm = (unsigned)bm0 | ((unsigned)bm1 << 1)
                    | ((unsigned)bm2 << 2) | ((unsigned)bm3 << 3);
        unsigned nn = (unsigned)bn0 | ((unsigned)bn1 << 1)
                    | ((unsigned)bn2 << 2) | ((unsigned)bn3 << 3);
        unsigned vm = nm << sh;
        unsigned vn = nn << sh;
        vm |= __shfl_xor_sync(0xffffffffu, vm, 1);
        vn |= __shfl_xor_sync(0xffffffffu, vn, 1);
        vm |= __shfl_xor_sync(0xffffffffu, vm, 2);
        vn |= __shfl_xor_sync(0xffffffffu, vn, 2);
        vm |= __shfl_xor_sync(0xffffffffu, vm, 4);
        vn |= __shfl_xor_sync(0xffffffffu, vn, 4);
        if ((lane & 7) == 0) {
            g_mask [(size_t)i*NW + k*4 + (lane>>3)] = vm;
            g_maskn[(size_t)i*NW + k*4 + (lane>>3)] = vn;
        }
    }
    float Sm = Sm0 + Sm1, Sn = Sn0 + Sn1;
    #pragma unroll
    for (int off = 16; off; off >>= 1) {
        Sm += __shfl_xor_sync(0xffffffffu, Sm, off);
        Sn += __shfl_xor_sync(0xffffffffu, Sn, off);
    }
    if (lane == 0) {
        g_km[i]  = (Sm > 0.f) ? 1.f / Sm : 0.f;
        g_kn[i]  = (Sn > 0.f) ? 1.f / Sn : 0.f;
        g_add[i] = ((Sm > 0.f) ? 0.f : INVN) + ((Sn > 0.f) ? 0.f : INVN);
        g_ep[i]  = ep;
        g_en[i]  = en;
    }
}

// ============================================================
// Kernel 3: fused attention + tf32 mma, cp.async double-buffer
// grid (KS, N/64); 128 thr = 4 warps x 16 rows
// B via pair-packed LDS.64; A = raw f32 bits (truncated tf32)
// ============================================================
#define WHS_SZ  18432
#define AT_OFF  36864
#define BD_OFF  54272
#define SMEM_SZ 55296
#define TL      ((N/KS)/64)

__device__ __forceinline__ float attn_val(float Bj, float Dj,
        float ep, float en, float km, float kn, float kmn, float add,
        unsigned mb, unsigned nb) {
    float ee = fmaxf(ep * Bj, en * Dj);
    float wsum = (mb & 1u) ? ((nb & 1u) ? kmn : km) : ((nb & 1u) ? kn : 0.f);
    return fmaf(ee, wsum, add);
}

__global__ void __launch_bounds__(128, 4) k_main(float* __restrict__ attn) {
    extern __shared__ char sm[];
    uint32_t sb = smem_u32(sm);

    int t = threadIdx.x, w = t >> 5, lane = t & 31;
    int g = lane >> 2, c = lane & 3;
    int i0 = blockIdx.y * 64;
    int rel0 = w*16 + g, rel1 = rel0 + 8;
    int r0 = i0 + rel0, r1 = i0 + rel1;
    int jcta = blockIdx.x * (N/KS);

    float ep0 = g_ep[r0], en0 = g_en[r0], km0 = g_km[r0], kn0 = g_kn[r0], add0 = g_add[r0];
    float ep1 = g_ep[r1], en1 = g_en[r1], km1 = g_km[r1], kn1 = g_kn[r1], add1 = g_add[r1];
    float kmn0 = km0 + kn0, kmn1 = km1 + kn1;

    float acc[8][4];
    #pragma unroll
    for (int nt = 0; nt < 8; nt++)
        #pragma unroll
        for (int q = 0; q < 4; q++) acc[nt][q] = 0.f;

    float* at_s = reinterpret_cast<float*>(sm + AT_OFF);

    // stage tile 0: pair-packed Wh (64 f x 32 pairs = 16KB payload, pad 36)
    {
        int b = jcta >> 6;
        #pragma unroll
        for (int q = 0; q < 8; q++) {
            int idx = t + 128*q;
            int f = idx >> 4, ch = idx & 15;
            cp16(sb + f*288 + ch*16, &g_Whp[(size_t)(b*64 + f)*32 + ch*2]);
        }
        if (t < 64) cp8(sb + BD_OFF + t*8, &g_BD[jcta + t]);
        asm volatile("cp.async.commit_group;" ::: "memory");
    }

    for (int tt = 0; tt < TL; tt++) {
        int buf = tt & 1;
        int j0  = jcta + tt*64;

        if (tt + 1 < TL) {
            int nb_ = (tt+1) & 1;
            int bn  = (j0 + 64) >> 6;
            #pragma unroll
            for (int q = 0; q < 8; q++) {
                int idx = t + 128*q;
                int f = idx >> 4, ch = idx & 15;
                cp16(sb + nb_*WHS_SZ + f*288 + ch*16, &g_Whp[(size_t)(bn*64 + f)*32 + ch*2]);
            }
            if (t < 64) cp8(sb + BD_OFF + nb_*512 + t*8, &g_BD[j0 + 64 + t]);
            asm volatile("cp.async.commit_group;" ::: "memory");
            asm volatile("cp.async.wait_group 1;" ::: "memory");
        } else {
            asm volatile("cp.async.wait_group 0;" ::: "memory");
        }
        __syncthreads();

        const uint2* whsp = reinterpret_cast<const uint2*>(sm + buf*WHS_SZ);
        const float2* BDs = reinterpret_cast<const float2*>(sm + BD_OFF + buf*512);

        int wb = j0 >> 5;
        uint2 mw0 = *reinterpret_cast<const uint2*>(&g_mask [(size_t)r0*NW + wb]);
        uint2 nw0 = *reinterpret_cast<const uint2*>(&g_maskn[(size_t)r0*NW + wb]);
        uint2 mw1 = *reinterpret_cast<const uint2*>(&g_mask [(size_t)r1*NW + wb]);
        uint2 nw1 = *reinterpret_cast<const uint2*>(&g_maskn[(size_t)r1*NW + wb]);

        #pragma unroll
        for (int kk = 0; kk < 8; kk++) {
            int jA = kk*8 + c, jB = jA + 4;
            float2 bdA = BDs[jA];
            float2 bdB = BDs[jB];
            unsigned m0 = (kk < 4) ? mw0.x : mw0.y;
            unsigned n0 = (kk < 4) ? nw0.x : nw0.y;
            unsigned m1 = (kk < 4) ? mw1.x : mw1.y;
            unsigned n1 = (kk < 4) ? nw1.x : nw1.y;
            int sA = (kk & 3)*8 + c, sB = sA + 4;

            float v00 = attn_val(bdA.x, bdA.y, ep0, en0, km0, kn0, kmn0, add0, m0>>sA, n0>>sA);
            float v10 = attn_val(bdA.x, bdA.y, ep1, en1, km1, kn1, kmn1, add1, m1>>sA, n1>>sA);
            float v01 = attn_val(bdB.x, bdB.y, ep0, en0, km0, kn0, kmn0, add0, m0>>sB, n0>>sB);
            float v11 = attn_val(bdB.x, bdB.y, ep1, en1, km1, kn1, kmn1, add1, m1>>sB, n1>>sB);

            at_s[rel0*68 + jA] = v00;  at_s[rel0*68 + jB] = v01;
            at_s[rel1*68 + jA] = v10;  at_s[rel1*68 + jB] = v11;

            // A operand: raw f32 bits (tf32 truncation)
            uint32_t a0 = __float_as_uint(v00), a1 = __float_as_uint(v10);
            uint32_t a2 = __float_as_uint(v01), a3 = __float_as_uint(v11);

            int pr = kk*4 + c;
            #pragma unroll
            for (int nt = 0; nt < 8; nt++) {
                uint2 b01 = whsp[(nt*8 + g)*36 + pr];
                mma_tf32(acc[nt], a0, a1, a2, a3, b01.x, b01.y);
            }
        }
        __syncthreads();

        #pragma unroll
        for (int q = 0; q < 8; q++) {
            int row = (t >> 4) + 8*q;
            int c4  = (t & 15) * 4;
            float4 v = *reinterpret_cast<const float4*>(&at_s[row*68 + c4]);
            *reinterpret_cast<float4*>(&attn[(size_t)(i0+row)*N + j0 + c4]) = v;
        }
    }

    #pragma unroll
    for (int nt = 0; nt < 8; nt++) {
        atomicAdd(&g_hp[(size_t)r0*FO + nt*8 + 2*c    ], acc[nt][0]);
        atomicAdd(&g_hp[(size_t)r0*FO + nt*8 + 2*c + 1], acc[nt][1]);
        atomicAdd(&g_hp[(size_t)r1*FO + nt*8 + 2*c    ], acc[nt][2]);
        atomicAdd(&g_hp[(size_t)r1*FO + nt*8 + 2*c + 1], acc[nt][3]);
    }
}

// ============================================================
// Kernel 4: out = elu(h_prime), float4
// ============================================================
__global__ void k_elu(float* __restrict__ out) {
    int tid = blockIdx.x * 256 + threadIdx.x;
    float4 x = reinterpret_cast<const float4*>(g_hp)[tid];
    x.x = x.x > 0.f ? x.x : expm1f(x.x);
    x.y = x.y > 0.f ? x.y : expm1f(x.y);
    x.z = x.z > 0.f ? x.z : expm1f(x.z);
    x.w = x.w > 0.f ? x.w : expm1f(x.w);
    reinterpret_cast<float4*>(out)[tid] = x;
}

// ============================================================
extern "C" void kernel_launch(void* const* d_in, const int* in_sizes, int n_in,
                              void* d_out, int out_size) {
    const float* h    = (const float*)d_in[0];
    const float* W    = (const float*)d_in[1];
    const float* a    = (const float*)d_in[2];
    const int*   adj  = (const int*)d_in[3];
    const int*   adjn = (const int*)d_in[4];

    float* out  = (float*)d_out;
    float* attn = out + (size_t)N * FO;

    cudaFuncSetAttribute(k_main, cudaFuncAttributeMaxDynamicSharedMemorySize, SMEM_SZ);

    k_gemm1<<<N/32, 128>>>(h, W, a);
    k_spack<<<N/8, 256>>>(adj, adjn);
    k_main<<<dim3(KS, N/64), 128, SMEM_SZ>>>(attn);
    k_elu<<<(N*FO)/1024, 256>>>(out);
}

// round 11
// speedup vs baseline: 1.8485x; 1.0230x over previous
#include <cuda_runtime.h>
#include <cstdint>

#define N     8192
#define FIN   512
#define FO    64
#define NW    256
#define INVN  (1.0f/8192.0f)
#define KS    8

// ---- scratch ----
__device__ uint2    g_Whp[N*32];      // pair-packed tf32 Wh: [jblk][f][pairidx]
__device__ float    g_Wh1[N];
__device__ float2   g_BD[N];          // (exp(wh2), exp(0.2*wh2))
__device__ float    g_add[N];
__device__ float    g_ep[N], g_en[N];
__device__ float    g_km[N], g_kn[N];
__device__ unsigned g_mask[N*NW];
__device__ unsigned g_maskn[N*NW];
__device__ float    g_hp[N*FO];

__device__ __forceinline__ uint32_t tf32bits(float x) {
    uint32_t r; asm("cvt.rna.tf32.f32 %0, %1;" : "=r"(r) : "f"(x)); return r;
}
__device__ __forceinline__ uint32_t smem_u32(const void* p) {
    uint32_t a;
    asm("{ .reg .u64 t; cvta.to.shared.u64 t, %1; cvt.u32.u64 %0, t; }" : "=r"(a) : "l"(p));
    return a;
}
__device__ __forceinline__ void cp16(uint32_t dst, const void* src) {
    asm volatile("cp.async.ca.shared.global [%0], [%1], 16;" :: "r"(dst), "l"(src));
}
__device__ __forceinline__ void cp8(uint32_t dst, const void* src) {
    asm volatile("cp.async.ca.shared.global [%0], [%1], 8;" :: "r"(dst), "l"(src));
}
__device__ __forceinline__ void mma_tf32(float* d,
        uint32_t a0, uint32_t a1, uint32_t a2, uint32_t a3,
        uint32_t b0, uint32_t b1) {
    asm volatile("mma.sync.aligned.m16n8k8.row.col.f32.tf32.tf32.f32 "
        "{%0,%1,%2,%3}, {%4,%5,%6,%7}, {%8,%9}, {%0,%1,%2,%3};"
        : "+f"(d[0]), "+f"(d[1]), "+f"(d[2]), "+f"(d[3])
        : "r"(a0), "r"(a1), "r"(a2), "r"(a3), "r"(b0), "r"(b1));
}
__device__ __forceinline__ int4 ldcs4(const int* p) {
    int4 v;
    asm volatile("ld.global.cs.v4.s32 {%0,%1,%2,%3}, [%4];"
        : "=r"(v.x), "=r"(v.y), "=r"(v.z), "=r"(v.w) : "l"(p));
    return v;
}

// ============================================================
// Kernel 1: Wh = h @ W (smem-tiled) + fused Wh1/Wh2/BD epilogue
// + pair-packed tf32 output g_Whp
// ============================================================
__global__ void __launch_bounds__(128) k_gemm1(const float* __restrict__ h,
                                               const float* __restrict__ W,
                                               const float* __restrict__ a) {
    __shared__ float Ws[64*64];
    __shared__ float hs[32*64];
    __shared__ float a_s[2*FO];

    int t = threadIdx.x;
    int f2 = t & 31, rg = t >> 5;
    int i0 = blockIdx.x * 32;
    if (t < 2*FO) a_s[t] = a[t];

    float acc[8][2];
    #pragma unroll
    for (int r = 0; r < 8; r++) { acc[r][0] = 0.f; acc[r][1] = 0.f; }

    for (int kt = 0; kt < 8; kt++) {
        __syncthreads();
        #pragma unroll
        for (int q = 0; q < 8; q++) {
            int idx = t + 128*q;
            int kk = idx >> 4, c4 = (idx & 15) * 4;
            *reinterpret_cast<float4*>(&Ws[kk*64 + c4]) =
                *reinterpret_cast<const float4*>(&W[(size_t)(kt*64 + kk)*FO + c4]);
        }
        #pragma unroll
        for (int q = 0; q < 4; q++) {
            int idx = t + 128*q;
            int row = idx >> 4, c4 = (idx & 15) * 4;
            *reinterpret_cast<float4*>(&hs[row*64 + c4]) =
                *reinterpret_cast<const float4*>(&h[(size_t)(i0+row)*FIN + kt*64 + c4]);
        }
        __syncthreads();

        #pragma unroll 8
        for (int kk = 0; kk < 64; kk++) {
            float w0 = Ws[kk*64 + f2];
            float w1 = Ws[kk*64 + f2 + 32];
            #pragma unroll
            for (int r = 0; r < 8; r++) {
                float hv = hs[(rg*8 + r)*64 + kk];
                acc[r][0] = fmaf(hv, w0, acc[r][0]);
                acc[r][1] = fmaf(hv, w1, acc[r][1]);
            }
        }
    }

    // pair-packed tf32 output: pairs (row jl, jl+4) at [b][col][idx]
    {
        int b = i0 >> 6;
        int jl_base = (i0 & 32) + rg*8;
        int idx0 = (jl_base >> 3) * 4;
        #pragma unroll
        for (int r = 0; r < 4; r++) {
            int idx = idx0 + r;
            g_Whp[(size_t)(b*64 + f2)*32 + idx] =
                make_uint2(tf32bits(acc[r][0]), tf32bits(acc[r+4][0]));
            g_Whp[(size_t)(b*64 + f2 + 32)*32 + idx] =
                make_uint2(tf32bits(acc[r][1]), tf32bits(acc[r+4][1]));
        }
    }

    // fused Wh1/Wh2/BD epilogue
    #pragma unroll
    for (int r = 0; r < 8; r++) {
        float p1 = acc[r][0] * a_s[f2] + acc[r][1] * a_s[f2 + 32];
        float p2 = acc[r][0] * a_s[64 + f2] + acc[r][1] * a_s[96 + f2];
        #pragma unroll
        for (int off = 16; off; off >>= 1) {
            p1 += __shfl_down_sync(0xffffffffu, p1, off);
            p2 += __shfl_down_sync(0xffffffffu, p2, off);
        }
        if (f2 == 0) {
            int row = i0 + rg*8 + r;
            g_Wh1[row] = p1;
            g_BD[row]  = make_float2(expf(p2), expf(0.2f * p2));
        }
    }
}

// ============================================================
// Kernel 2: FUSED adj pass: ballot-pack + softmax sums
// ============================================================
__global__ void k_spack(const int* __restrict__ adj,
                        const int* __restrict__ adjn) {
    int tid = blockIdx.x * 256 + threadIdx.x;
    g_hp[2*tid]     = 0.f;
    g_hp[2*tid + 1] = 0.f;

    int lane = threadIdx.x & 31;
    int i    = blockIdx.x * 8 + (threadIdx.x >> 5);
    float wh1 = g_Wh1[i];
    float ep = expf(wh1);
    float en = expf(0.2f * wh1);
    const int* arow = adj  + (size_t)i * N;
    const int* nrow = adjn + (size_t)i * N;
    int sh = (lane & 7) * 4;

    float Sm0 = 0.f, Sm1 = 0.f, Sn0 = 0.f, Sn1 = 0.f;

    #pragma unroll 4
    for (int k = 0; k < N/128; k++) {
        int jb = k*128 + lane*4;
        int4   av  = ldcs4(&arow[jb]);
        int4   nv  = ldcs4(&nrow[jb]);
        float4 bd0 = *reinterpret_cast<const float4*>(&g_BD[jb]);
        float4 bd1 = *reinterpret_cast<const float4*>(&g_BD[jb + 2]);

        float v0 = fmaxf(ep*bd0.x, en*bd0.y);
        float v1 = fmaxf(ep*bd0.z, en*bd0.w);
        float v2 = fmaxf(ep*bd1.x, en*bd1.y);
        float v3 = fmaxf(ep*bd1.z, en*bd1.w);

        bool bm0 = av.x > 0, bm1 = av.y > 0, bm2 = av.z > 0, bm3 = av.w > 0;
        bool bn0 = nv.x > 0, bn1 = nv.y > 0, bn2 = nv.z > 0, bn3 = nv.w > 0;

        if (bm0) Sm0 += v0;   if (bm1) Sm1 += v1;
        if (bm2) Sm0 += v2;   if (bm3) Sm1 += v3;
        if (bn0) Sn0 += v0;   if (bn1) Sn1 += v1;
        if (bn2) Sn0 += v2;   if (bn3) Sn1 += v3;

        unsigned nm = (unsigned)bm0 | ((unsigned)bm1 << 1)
                    | ((unsigned)bm2 << 2) | ((unsigned)bm3 << 3);
        unsigned nn = (unsigned)bn0 | ((unsigned)bn1 << 1)
                    | ((unsigned)bn2 << 2) | ((unsigned)bn3 << 3);
        unsigned vm = nm << sh;
        unsigned vn = nn << sh;
        vm |= __shfl_xor_sync(0xffffffffu, vm, 1);
        vn |= __shfl_xor_sync(0xffffffffu, vn, 1);
        vm |= __shfl_xor_sync(0xffffffffu, vm, 2);
        vn |= __shfl_xor_sync(0xffffffffu, vn, 2);
        vm |= __shfl_xor_sync(0xffffffffu, vm, 4);
        vn |= __shfl_xor_sync(0xffffffffu, vn, 4);
        if ((lane & 7) == 0) {
            g_mask [(size_t)i*NW + k*4 + (lane>>3)] = vm;
            g_maskn[(size_t)i*NW + k*4 + (lane>>3)] = vn;
        }
    }
    float Sm = Sm0 + Sm1, Sn = Sn0 + Sn1;
    #pragma unroll
    for (int off = 16; off; off >>= 1) {
        Sm += __shfl_xor_sync(0xffffffffu, Sm, off);
        Sn += __shfl_xor_sync(0xffffffffu, Sn, off);
    }
    if (lane == 0) {
        g_km[i]  = (Sm > 0.f) ? 1.f / Sm : 0.f;
        g_kn[i]  = (Sn > 0.f) ? 1.f / Sn : 0.f;
        g_add[i] = ((Sm > 0.f) ? 0.f : INVN) + ((Sn > 0.f) ? 0.f : INVN);
        g_ep[i]  = ep;
        g_en[i]  = en;
    }
}

// ============================================================
// Kernel 3: fused attention + tf32 mma, cp.async double-buffer
// grid (KS=8, N/64); 128 thr = 4 warps x 16 rows
// masks software-pipelined one tile ahead
// ============================================================
#define WHS_SZ  18432
#define AT_OFF  36864
#define BD_OFF  54272
#define SMEM_SZ 55296
#define TL      ((N/KS)/64)

__device__ __forceinline__ float attn_val(float Bj, float Dj,
        float ep, float en, float km, float kn, float kmn, float add,
        unsigned mb, unsigned nb) {
    float ee = fmaxf(ep * Bj, en * Dj);
    float wsum = (mb & 1u) ? ((nb & 1u) ? kmn : km) : ((nb & 1u) ? kn : 0.f);
    return fmaf(ee, wsum, add);
}

__global__ void __launch_bounds__(128, 4) k_main(float* __restrict__ attn) {
    extern __shared__ char sm[];
    uint32_t sb = smem_u32(sm);

    int t = threadIdx.x, w = t >> 5, lane = t & 31;
    int g = lane >> 2, c = lane & 3;
    int i0 = blockIdx.y * 64;
    int rel0 = w*16 + g, rel1 = rel0 + 8;
    int r0 = i0 + rel0, r1 = i0 + rel1;
    int jcta = blockIdx.x * (N/KS);

    float ep0 = g_ep[r0], en0 = g_en[r0], km0 = g_km[r0], kn0 = g_kn[r0], add0 = g_add[r0];
    float ep1 = g_ep[r1], en1 = g_en[r1], km1 = g_km[r1], kn1 = g_kn[r1], add1 = g_add[r1];
    float kmn0 = km0 + kn0, kmn1 = km1 + kn1;

    float acc[8][4];
    #pragma unroll
    for (int nt = 0; nt < 8; nt++)
        #pragma unroll
        for (int q = 0; q < 4; q++) acc[nt][q] = 0.f;

    float* at_s = reinterpret_cast<float*>(sm + AT_OFF);

    // stage tile 0 + masks for tile 0
    {
        int b = jcta >> 6;
        #pragma unroll
        for (int q = 0; q < 8; q++) {
            int idx = t + 128*q;
            int f = idx >> 4, ch = idx & 15;
            cp16(sb + f*288 + ch*16, &g_Whp[(size_t)(b*64 + f)*32 + ch*2]);
        }
        if (t < 64) cp8(sb + BD_OFF + t*8, &g_BD[jcta + t]);
        asm volatile("cp.async.commit_group;" ::: "memory");
    }
    int wb0 = jcta >> 5;
    uint2 mw0 = *reinterpret_cast<const uint2*>(&g_mask [(size_t)r0*NW + wb0]);
    uint2 nw0 = *reinterpret_cast<const uint2*>(&g_maskn[(size_t)r0*NW + wb0]);
    uint2 mw1 = *reinterpret_cast<const uint2*>(&g_mask [(size_t)r1*NW + wb0]);
    uint2 nw1 = *reinterpret_cast<const uint2*>(&g_maskn[(size_t)r1*NW + wb0]);

    for (int tt = 0; tt < TL; tt++) {
        int buf = tt & 1;
        int j0  = jcta + tt*64;

        uint2 mw0n, nw0n, mw1n, nw1n;
        if (tt + 1 < TL) {
            int nb_ = (tt+1) & 1;
            int bn  = (j0 + 64) >> 6;
            #pragma unroll
            for (int q = 0; q < 8; q++) {
                int idx = t + 128*q;
                int f = idx >> 4, ch = idx & 15;
                cp16(sb + nb_*WHS_SZ + f*288 + ch*16, &g_Whp[(size_t)(bn*64 + f)*32 + ch*2]);
            }
            if (t < 64) cp8(sb + BD_OFF + nb_*512 + t*8, &g_BD[j0 + 64 + t]);
            asm volatile("cp.async.commit_group;" ::: "memory");
            // prefetch masks for next tile (consumed next iteration)
            int wbn = (j0 + 64) >> 5;
            mw0n = *reinterpret_cast<const uint2*>(&g_mask [(size_t)r0*NW + wbn]);
            nw0n = *reinterpret_cast<const uint2*>(&g_maskn[(size_t)r0*NW + wbn]);
            mw1n = *reinterpret_cast<const uint2*>(&g_mask [(size_t)r1*NW + wbn]);
            nw1n = *reinterpret_cast<const uint2*>(&g_maskn[(size_t)r1*NW + wbn]);
            asm volatile("cp.async.wait_group 1;" ::: "memory");
        } else {
            mw0n = make_uint2(0,0); nw0n = mw0n; mw1n = mw0n; nw1n = mw0n;
            asm volatile("cp.async.wait_group 0;" ::: "memory");
        }
        __syncthreads();

        const uint2* whsp = reinterpret_cast<const uint2*>(sm + buf*WHS_SZ);
        const float2* BDs = reinterpret_cast<const float2*>(sm + BD_OFF + buf*512);

        #pragma unroll
        for (int kk = 0; kk < 8; kk++) {
            int jA = kk*8 + c, jB = jA + 4;
            float2 bdA = BDs[jA];
            float2 bdB = BDs[jB];
            unsigned m0 = (kk < 4) ? mw0.x : mw0.y;
            unsigned n0 = (kk < 4) ? nw0.x : nw0.y;
            unsigned m1 = (kk < 4) ? mw1.x : mw1.y;
            unsigned n1 = (kk < 4) ? nw1.x : nw1.y;
            int sA = (kk & 3)*8 + c, sB = sA + 4;

            float v00 = attn_val(bdA.x, bdA.y, ep0, en0, km0, kn0, kmn0, add0, m0>>sA, n0>>sA);
            float v10 = attn_val(bdA.x, bdA.y, ep1, en1, km1, kn1, kmn1, add1, m1>>sA, n1>>sA);
            float v01 = attn_val(bdB.x, bdB.y, ep0, en0, km0, kn0, kmn0, add0, m0>>sB, n0>>sB);
            float v11 = attn_val(bdB.x, bdB.y, ep1, en1, km1, kn1, kmn1, add1, m1>>sB, n1>>sB);

            at_s[rel0*68 + jA] = v00;  at_s[rel0*68 + jB] = v01;
            at_s[rel1*68 + jA] = v10;  at_s[rel1*68 + jB] = v11;

            uint32_t a0 = tf32bits(v00), a1 = tf32bits(v10);
            uint32_t a2 = tf32bits(v01), a3 = tf32bits(v11);

            int pr = kk*4 + c;
            #pragma unroll
            for (int nt = 0; nt < 8; nt++) {
                uint2 b01 = whsp[(nt*8 + g)*36 + pr];
                mma_tf32(acc[nt], a0, a1, a2, a3, b01.x, b01.y);
            }
        }
        mw0 = mw0n; nw0 = nw0n; mw1 = mw1n; nw1 = nw1n;
        __syncthreads();

        #pragma unroll
        for (int q = 0; q < 8; q++) {
            int row = (t >> 4) + 8*q;
            int c4  = (t & 15) * 4;
            float4 v = *reinterpret_cast<const float4*>(&at_s[row*68 + c4]);
            *reinterpret_cast<float4*>(&attn[(size_t)(i0+row)*N + j0 + c4]) = v;
        }
    }

    #pragma unroll
    for (int nt = 0; nt < 8; nt++) {
        atomicAdd(&g_hp[(size_t)r0*FO + nt*8 + 2*c    ], acc[nt][0]);
        atomicAdd(&g_hp[(size_t)r0*FO + nt*8 + 2*c + 1], acc[nt][1]);
        atomicAdd(&g_hp[(size_t)r1*FO + nt*8 + 2*c    ], acc[nt][2]);
        atomicAdd(&g_hp[(size_t)r1*FO + nt*8 + 2*c + 1], acc[nt][3]);
    }
}

// ============================================================
// Kernel 4: out = elu(h_prime), float4
// ============================================================
__global__ void k_elu(float* __restrict__ out) {
    int tid = blockIdx.x * 256 + threadIdx.x;
    float4 x = reinterpret_cast<const float4*>(g_hp)[tid];
    x.x = x.x > 0.f ? x.x : expm1f(x.x);
    x.y = x.y > 0.f ? x.y : expm1f(x.y);
    x.z = x.z > 0.f ? x.z : expm1f(x.z);
    x.w = x.w > 0.f ? x.w : expm1f(x.w);
    reinterpret_cast<float4*>(out)[tid] = x;
}

// ============================================================
extern "C" void kernel_launch(void* const* d_in, const int* in_sizes, int n_in,
                              void* d_out, int out_size) {
    const float* h    = (const float*)d_in[0];
    const float* W    = (const float*)d_in[1];
    const float* a    = (const float*)d_in[2];
    const int*   adj  = (const int*)d_in[3];
    const int*   adjn = (const int*)d_in[4];

    float* out  = (float*)d_out;
    float* attn = out + (size_t)N * FO;

    cudaFuncSetAttribute(k_main, cudaFuncAttributeMaxDynamicSharedMemorySize, SMEM_SZ);

    k_gemm1<<<N/32, 128>>>(h, W, a);
    k_spack<<<N/8, 256>>>(adj, adjn);
    k_main<<<dim3(KS, N/64), 128, SMEM_SZ>>>(attn);
    k_elu<<<(N*FO)/1024, 256>>>(out);
}

// round 12
// speedup vs baseline: 1.8869x; 1.0208x over previous
#include <cuda_runtime.h>
#include <cstdint>

#define N     8192
#define FIN   512
#define FO    64
#define NW    256
#define INVN  (1.0f/8192.0f)
#define KS    8

// ---- scratch ----
__device__ uint32_t g_Whb[N*32];      // bf16x2-pair-packed Wh: [jblk][f][idx2]
__device__ float    g_Wh1[N];
__device__ float2   g_BD[N];          // (exp(wh2), exp(0.2*wh2))
__device__ float    g_add[N];
__device__ float    g_ep[N], g_en[N];
__device__ float    g_km[N], g_kn[N];
__device__ unsigned g_mask[N*NW];
__device__ unsigned g_maskn[N*NW];
__device__ float    g_hp[N*FO];

__device__ __forceinline__ uint32_t bf16x2(float lo, float hi) {
    uint32_t r; asm("cvt.rn.bf16x2.f32 %0, %1, %2;" : "=r"(r) : "f"(hi), "f"(lo)); return r;
}
__device__ __forceinline__ uint32_t smem_u32(const void* p) {
    uint32_t a;
    asm("{ .reg .u64 t; cvta.to.shared.u64 t, %1; cvt.u32.u64 %0, t; }" : "=r"(a) : "l"(p));
    return a;
}
__device__ __forceinline__ void cp16(uint32_t dst, const void* src) {
    asm volatile("cp.async.ca.shared.global [%0], [%1], 16;" :: "r"(dst), "l"(src));
}
__device__ __forceinline__ void cp8(uint32_t dst, const void* src) {
    asm volatile("cp.async.ca.shared.global [%0], [%1], 8;" :: "r"(dst), "l"(src));
}
__device__ __forceinline__ void mma_bf16(float* d,
        uint32_t a0, uint32_t a1, uint32_t a2, uint32_t a3,
        uint32_t b0, uint32_t b1) {
    asm volatile("mma.sync.aligned.m16n8k16.row.col.f32.bf16.bf16.f32 "
        "{%0,%1,%2,%3}, {%4,%5,%6,%7}, {%8,%9}, {%0,%1,%2,%3};"
        : "+f"(d[0]), "+f"(d[1]), "+f"(d[2]), "+f"(d[3])
        : "r"(a0), "r"(a1), "r"(a2), "r"(a3), "r"(b0), "r"(b1));
}
__device__ __forceinline__ int4 ldcs4(const int* p) {
    int4 v;
    asm volatile("ld.global.cs.v4.s32 {%0,%1,%2,%3}, [%4];"
        : "=r"(v.x), "=r"(v.y), "=r"(v.z), "=r"(v.w) : "l"(p));
    return v;
}

// ============================================================
// Kernel 1: Wh = h @ W (smem-tiled) + Wh1/Wh2/BD epilogue
// + bf16x2-pair-packed output g_Whb
// ============================================================
__global__ void __launch_bounds__(128) k_gemm1(const float* __restrict__ h,
                                               const float* __restrict__ W,
                                               const float* __restrict__ a) {
    __shared__ float Ws[64*64];
    __shared__ float hs[32*64];
    __shared__ float a_s[2*FO];

    int t = threadIdx.x;
    int f2 = t & 31, rg = t >> 5;
    int i0 = blockIdx.x * 32;
    if (t < 2*FO) a_s[t] = a[t];

    float acc[8][2];
    #pragma unroll
    for (int r = 0; r < 8; r++) { acc[r][0] = 0.f; acc[r][1] = 0.f; }

    for (int kt = 0; kt < 8; kt++) {
        __syncthreads();
        #pragma unroll
        for (int q = 0; q < 8; q++) {
            int idx = t + 128*q;
            int kk = idx >> 4, c4 = (idx & 15) * 4;
            *reinterpret_cast<float4*>(&Ws[kk*64 + c4]) =
                *reinterpret_cast<const float4*>(&W[(size_t)(kt*64 + kk)*FO + c4]);
        }
        #pragma unroll
        for (int q = 0; q < 4; q++) {
            int idx = t + 128*q;
            int row = idx >> 4, c4 = (idx & 15) * 4;
            *reinterpret_cast<float4*>(&hs[row*64 + c4]) =
                *reinterpret_cast<const float4*>(&h[(size_t)(i0+row)*FIN + kt*64 + c4]);
        }
        __syncthreads();

        #pragma unroll 8
        for (int kk = 0; kk < 64; kk++) {
            float w0 = Ws[kk*64 + f2];
            float w1 = Ws[kk*64 + f2 + 32];
            #pragma unroll
            for (int r = 0; r < 8; r++) {
                float hv = hs[(rg*8 + r)*64 + kk];
                acc[r][0] = fmaf(hv, w0, acc[r][0]);
                acc[r][1] = fmaf(hv, w1, acc[r][1]);
            }
        }
    }

    // bf16x2-pair-packed output for m16n8k16 B fragments
    {
        int b    = i0 >> 6;
        int base = (i0 & 32) + rg*8;       // local j of acc[0] within 64-block
        int kk2  = base >> 4;
        int hh   = (base >> 3) & 1;        // k-half (j offset 0-7 vs 8-15)
        #pragma unroll
        for (int c = 0; c < 4; c++) {
            int idx2 = (kk2*4 + c)*2 + hh;
            g_Whb[(size_t)(b*64 + f2)*32 + idx2]      = bf16x2(acc[2*c][0], acc[2*c+1][0]);
            g_Whb[(size_t)(b*64 + f2 + 32)*32 + idx2] = bf16x2(acc[2*c][1], acc[2*c+1][1]);
        }
    }

    // fused Wh1/Wh2/BD epilogue
    #pragma unroll
    for (int r = 0; r < 8; r++) {
        float p1 = acc[r][0] * a_s[f2] + acc[r][1] * a_s[f2 + 32];
        float p2 = acc[r][0] * a_s[64 + f2] + acc[r][1] * a_s[96 + f2];
        #pragma unroll
        for (int off = 16; off; off >>= 1) {
            p1 += __shfl_down_sync(0xffffffffu, p1, off);
            p2 += __shfl_down_sync(0xffffffffu, p2, off);
        }
        if (f2 == 0) {
            int row = i0 + rg*8 + r;
            g_Wh1[row] = p1;
            g_BD[row]  = make_float2(expf(p2), expf(0.2f * p2));
        }
    }
}

// ============================================================
// Kernel 2: FUSED adj pass: ballot-pack + softmax sums
// ============================================================
__global__ void k_spack(const int* __restrict__ adj,
                        const int* __restrict__ adjn) {
    int tid = blockIdx.x * 256 + threadIdx.x;
    g_hp[2*tid]     = 0.f;
    g_hp[2*tid + 1] = 0.f;

    int lane = threadIdx.x & 31;
    int i    = blockIdx.x * 8 + (threadIdx.x >> 5);
    float wh1 = g_Wh1[i];
    float ep = expf(wh1);
    float en = expf(0.2f * wh1);
    const int* arow = adj  + (size_t)i * N;
    const int* nrow = adjn + (size_t)i * N;
    int sh = (lane & 7) * 4;

    float Sm0 = 0.f, Sm1 = 0.f, Sn0 = 0.f, Sn1 = 0.f;

    #pragma unroll 8
    for (int k = 0; k < N/128; k++) {
        int jb = k*128 + lane*4;
        int4   av  = ldcs4(&arow[jb]);
        int4   nv  = ldcs4(&nrow[jb]);
        float4 bd0 = *reinterpret_cast<const float4*>(&g_BD[jb]);
        float4 bd1 = *reinterpret_cast<const float4*>(&g_BD[jb + 2]);

        float v0 = fmaxf(ep*bd0.x, en*bd0.y);
        float v1 = fmaxf(ep*bd0.z, en*bd0.w);
        float v2 = fmaxf(ep*bd1.x, en*bd1.y);
        float v3 = fmaxf(ep*bd1.z, en*bd1.w);

        bool bm0 = av.x > 0, bm1 = av.y > 0, bm2 = av.z > 0, bm3 = av.w > 0;
        bool bn0 = nv.x > 0, bn1 = nv.y > 0, bn2 = nv.z > 0, bn3 = nv.w > 0;

        if (bm0) Sm0 += v0;   if (bm1) Sm1 += v1;
        if (bm2) Sm0 += v2;   if (bm3) Sm1 += v3;
        if (bn0) Sn0 += v0;   if (bn1) Sn1 += v1;
        if (bn2) Sn0 += v2;   if (bn3) Sn1 += v3;

        unsigned nm = (unsigned)bm0 | ((unsigned)bm1 << 1)
                    | ((unsigned)bm2 << 2) | ((unsigned)bm3 << 3);
        unsigned nn = (unsigned)bn0 | ((unsigned)bn1 << 1)
                    | ((unsigned)bn2 << 2) | ((unsigned)bn3 << 3);
        unsigned vm = nm << sh;
        unsigned vn = nn << sh;
        vm |= __shfl_xor_sync(0xffffffffu, vm, 1);
        vn |= __shfl_xor_sync(0xffffffffu, vn, 1);
        vm |= __shfl_xor_sync(0xffffffffu, vm, 2);
        vn |= __shfl_xor_sync(0xffffffffu, vn, 2);
        vm |= __shfl_xor_sync(0xffffffffu, vm, 4);
        vn |= __shfl_xor_sync(0xffffffffu, vn, 4);
        if ((lane & 7) == 0) {
            g_mask [(size_t)i*NW + k*4 + (lane>>3)] = vm;
            g_maskn[(size_t)i*NW + k*4 + (lane>>3)] = vn;
        }
    }
    float Sm = Sm0 + Sm1, Sn = Sn0 + Sn1;
    #pragma unroll
    for (int off = 16; off; off >>= 1) {
        Sm += __shfl_xor_sync(0xffffffffu, Sm, off);
        Sn += __shfl_xor_sync(0xffffffffu, Sn, off);
    }
    if (lane == 0) {
        g_km[i]  = (Sm > 0.f) ? 1.f / Sm : 0.f;
        g_kn[i]  = (Sn > 0.f) ? 1.f / Sn : 0.f;
        g_add[i] = ((Sm > 0.f) ? 0.f : INVN) + ((Sn > 0.f) ? 0.f : INVN);
        g_ep[i]  = ep;
        g_en[i]  = en;
    }
}

// ============================================================
// Kernel 3: fused attention + bf16 m16n8k16 mma, cp.async pipe
// grid (KS=8, N/64); 128 thr = 4 warps x 16 rows; 5 CTAs/SM
// ============================================================
#define WHS_SZ  9216                   // 64 f x 18 uint2
#define AT_OFF  18432
#define BD_OFF  35840
#define SMEM_SZ 36864
#define TL      ((N/KS)/64)

__device__ __forceinline__ float attn_val(float Bj, float Dj,
        float ep, float en, float km, float kn, float kmn, float add,
        unsigned mb, unsigned nb) {
    float ee = fmaxf(ep * Bj, en * Dj);
    float wsum = (mb & 1u) ? ((nb & 1u) ? kmn : km) : ((nb & 1u) ? kn : 0.f);
    return fmaf(ee, wsum, add);
}

__global__ void __launch_bounds__(128, 5) k_main(float* __restrict__ attn) {
    extern __shared__ char sm[];
    uint32_t sb = smem_u32(sm);

    int t = threadIdx.x, w = t >> 5, lane = t & 31;
    int g = lane >> 2, c = lane & 3;
    int i0 = blockIdx.y * 64;
    int rel0 = w*16 + g, rel1 = rel0 + 8;
    int r0 = i0 + rel0, r1 = i0 + rel1;
    int jcta = blockIdx.x * (N/KS);

    float ep0 = g_ep[r0], en0 = g_en[r0], km0 = g_km[r0], kn0 = g_kn[r0], add0 = g_add[r0];
    float ep1 = g_ep[r1], en1 = g_en[r1], km1 = g_km[r1], kn1 = g_kn[r1], add1 = g_add[r1];
    float kmn0 = km0 + kn0, kmn1 = km1 + kn1;

    float acc[8][4];
    #pragma unroll
    for (int nt = 0; nt < 8; nt++)
        #pragma unroll
        for (int q = 0; q < 4; q++) acc[nt][q] = 0.f;

    float* at_s = reinterpret_cast<float*>(sm + AT_OFF);

    // stage tile 0 (bf16 Whb: 64 f x 128B, row stride 144B)
    {
        int b = jcta >> 6;
        #pragma unroll
        for (int q = 0; q < 4; q++) {
            int idx = t + 128*q;
            int f = idx >> 3, ch = idx & 7;
            cp16(sb + f*144 + ch*16, &g_Whb[(size_t)(b*64 + f)*32 + ch*4]);
        }
        if (t < 64) cp8(sb + BD_OFF + t*8, &g_BD[jcta + t]);
        asm volatile("cp.async.commit_group;" ::: "memory");
    }
    int wb0 = jcta >> 5;
    uint2 mw0 = *reinterpret_cast<const uint2*>(&g_mask [(size_t)r0*NW + wb0]);
    uint2 nw0 = *reinterpret_cast<const uint2*>(&g_maskn[(size_t)r0*NW + wb0]);
    uint2 mw1 = *reinterpret_cast<const uint2*>(&g_mask [(size_t)r1*NW + wb0]);
    uint2 nw1 = *reinterpret_cast<const uint2*>(&g_maskn[(size_t)r1*NW + wb0]);

    for (int tt = 0; tt < TL; tt++) {
        int buf = tt & 1;
        int j0  = jcta + tt*64;

        uint2 mw0n, nw0n, mw1n, nw1n;
        if (tt + 1 < TL) {
            int nb_ = (tt+1) & 1;
            int bn  = (j0 + 64) >> 6;
            #pragma unroll
            for (int q = 0; q < 4; q++) {
                int idx = t + 128*q;
                int f = idx >> 3, ch = idx & 7;
                cp16(sb + nb_*WHS_SZ + f*144 + ch*16, &g_Whb[(size_t)(bn*64 + f)*32 + ch*4]);
            }
            if (t < 64) cp8(sb + BD_OFF + nb_*512 + t*8, &g_BD[j0 + 64 + t]);
            asm volatile("cp.async.commit_group;" ::: "memory");
            int wbn = (j0 + 64) >> 5;
            mw0n = *reinterpret_cast<const uint2*>(&g_mask [(size_t)r0*NW + wbn]);
            nw0n = *reinterpret_cast<const uint2*>(&g_maskn[(size_t)r0*NW + wbn]);
            mw1n = *reinterpret_cast<const uint2*>(&g_mask [(size_t)r1*NW + wbn]);
            nw1n = *reinterpret_cast<const uint2*>(&g_maskn[(size_t)r1*NW + wbn]);
            asm volatile("cp.async.wait_group 1;" ::: "memory");
        } else {
            mw0n = make_uint2(0,0); nw0n = mw0n; mw1n = mw0n; nw1n = mw0n;
            asm volatile("cp.async.wait_group 0;" ::: "memory");
        }
        __syncthreads();

        const uint2*  whsp = reinterpret_cast<const uint2*>(sm + buf*WHS_SZ);
        const float2* BDs  = reinterpret_cast<const float2*>(sm + BD_OFF + buf*512);

        #pragma unroll
        for (int kk2 = 0; kk2 < 4; kk2++) {
            int jA = kk2*16 + 2*c;      // j, j+1
            int jB = jA + 8;            // j+8, j+9
            float4 bdA = *reinterpret_cast<const float4*>(&BDs[jA]);
            float4 bdB = *reinterpret_cast<const float4*>(&BDs[jB]);
            unsigned m0 = (kk2 < 2) ? mw0.x : mw0.y;
            unsigned n0 = (kk2 < 2) ? nw0.x : nw0.y;
            unsigned m1 = (kk2 < 2) ? mw1.x : mw1.y;
            unsigned n1 = (kk2 < 2) ? nw1.x : nw1.y;
            int sA = (kk2 & 1)*16 + 2*c, sB = sA + 8;

            float v00 = attn_val(bdA.x, bdA.y, ep0, en0, km0, kn0, kmn0, add0, m0>>sA,     n0>>sA);
            float v01 = attn_val(bdA.z, bdA.w, ep0, en0, km0, kn0, kmn0, add0, m0>>(sA+1), n0>>(sA+1));
            float v02 = attn_val(bdB.x, bdB.y, ep0, en0, km0, kn0, kmn0, add0, m0>>sB,     n0>>sB);
            float v03 = attn_val(bdB.z, bdB.w, ep0, en0, km0, kn0, kmn0, add0, m0>>(sB+1), n0>>(sB+1));
            float v10 = attn_val(bdA.x, bdA.y, ep1, en1, km1, kn1, kmn1, add1, m1>>sA,     n1>>sA);
            float v11 = attn_val(bdA.z, bdA.w, ep1, en1, km1, kn1, kmn1, add1, m1>>(sA+1), n1>>(sA+1));
            float v12 = attn_val(bdB.x, bdB.y, ep1, en1, km1, kn1, kmn1, add1, m1>>sB,     n1>>sB);
            float v13 = attn_val(bdB.z, bdB.w, ep1, en1, km1, kn1, kmn1, add1, m1>>(sB+1), n1>>(sB+1));

            // exact fp32 attention -> smem (STS.64, adjacent j)
            *reinterpret_cast<float2*>(&at_s[rel0*68 + jA]) = make_float2(v00, v01);
            *reinterpret_cast<float2*>(&at_s[rel0*68 + jB]) = make_float2(v02, v03);
            *reinterpret_cast<float2*>(&at_s[rel1*68 + jA]) = make_float2(v10, v11);
            *reinterpret_cast<float2*>(&at_s[rel1*68 + jB]) = make_float2(v12, v13);

            uint32_t a0 = bf16x2(v00, v01);
            uint32_t a1 = bf16x2(v10, v11);
            uint32_t a2 = bf16x2(v02, v03);
            uint32_t a3 = bf16x2(v12, v13);

            #pragma unroll
            for (int nt = 0; nt < 8; nt++) {
                uint2 b01 = whsp[(nt*8 + g)*18 + kk2*4 + c];
                mma_bf16(acc[nt], a0, a1, a2, a3, b01.x, b01.y);
            }
        }
        mw0 = mw0n; nw0 = nw0n; mw1 = mw1n; nw1 = nw1n;
        __syncthreads();

        #pragma unroll
        for (int q = 0; q < 8; q++) {
            int row = (t >> 4) + 8*q;
            int c4  = (t & 15) * 4;
            float4 v = *reinterpret_cast<const float4*>(&at_s[row*68 + c4]);
            *reinterpret_cast<float4*>(&attn[(size_t)(i0+row)*N + j0 + c4]) = v;
        }
    }

    #pragma unroll
    for (int nt = 0; nt < 8; nt++) {
        atomicAdd(&g_hp[(size_t)r0*FO + nt*8 + 2*c    ], acc[nt][0]);
        atomicAdd(&g_hp[(size_t)r0*FO + nt*8 + 2*c + 1], acc[nt][1]);
        atomicAdd(&g_hp[(size_t)r1*FO + nt*8 + 2*c    ], acc[nt][2]);
        atomicAdd(&g_hp[(size_t)r1*FO + nt*8 + 2*c + 1], acc[nt][3]);
    }
}

// ============================================================
// Kernel 4: out = elu(h_prime), float4
// ============================================================
__global__ void k_elu(float* __restrict__ out) {
    int tid = blockIdx.x * 256 + threadIdx.x;
    float4 x = reinterpret_cast<const float4*>(g_hp)[tid];
    x.x = x.x > 0.f ? x.x : expm1f(x.x);
    x.y = x.y > 0.f ? x.y : expm1f(x.y);
    x.z = x.z > 0.f ? x.z : expm1f(x.z);
    x.w = x.w > 0.f ? x.w : expm1f(x.w);
    reinterpret_cast<float4*>(out)[tid] = x;
}

// ============================================================
extern "C" void kernel_launch(void* const* d_in, const int* in_sizes, int n_in,
                              void* d_out, int out_size) {
    const float* h    = (const float*)d_in[0];
    const float* W    = (const float*)d_in[1];
    const float* a    = (const float*)d_in[2];
    const int*   adj  = (const int*)d_in[3];
    const int*   adjn = (const int*)d_in[4];

    float* out  = (float*)d_out;
    float* attn = out + (size_t)N * FO;

    cudaFuncSetAttribute(k_main, cudaFuncAttributeMaxDynamicSharedMemorySize, SMEM_SZ);

    k_gemm1<<<N/32, 128>>>(h, W, a);
    k_spack<<<N/8, 256>>>(adj, adjn);
    k_main<<<dim3(KS, N/64), 128, SMEM_SZ>>>(attn);
    k_elu<<<(N*FO)/1024, 256>>>(out);
}